// round 11
// baseline (speedup 1.0000x reference)
#include <cuda_runtime.h>
#include <cuda_bf16.h>
#include <math.h>
#include <stdint.h>

#define N_ATOMS 40000
#define N_BONDS 90000
#define MAX_NB 6
#define ATOM_FDIM 133
#define BOND_FDIM 147
#define HID 300
#define DEPTH 6
#define CAT_DIM (ATOM_FDIM + HID)   // 433

#define H4   (HID / 4)              // 75
#define H34  (3 * HID / 4)          // 225

// padded K strides (multiples of 32) for bf16 split operands
#define KP_BOND 160                 // 147 -> 160
#define KP_HID  320                 // 300 -> 320
#define KP_CAT  448                 // 433 -> 448

// ---------------- scratch (device globals; no cudaMalloc allowed) -------------
__device__ float g_inp [N_BONDS * HID];
__device__ float g_gi  [N_BONDS * 3 * HID];
__device__ float g_msg [N_BONDS * HID];
__device__ float g_gh  [N_BONDS * 3 * HID];
__device__ float g_amsg[N_ATOMS * HID];

__device__ __nv_bfloat16 g_fb_hi [N_BONDS * KP_BOND];
__device__ __nv_bfloat16 g_fb_lo [N_BONDS * KP_BOND];
__device__ __nv_bfloat16 g_inp_hi[N_BONDS * KP_HID];
__device__ __nv_bfloat16 g_inp_lo[N_BONDS * KP_HID];
__device__ __nv_bfloat16 g_h_hi  [N_BONDS * KP_HID];
__device__ __nv_bfloat16 g_h_lo  [N_BONDS * KP_HID];
__device__ __nv_bfloat16 g_ain_hi[N_ATOMS * KP_CAT];
__device__ __nv_bfloat16 g_ain_lo[N_ATOMS * KP_CAT];
__device__ __nv_bfloat16 g_Wi_hi [HID * KP_BOND];
__device__ __nv_bfloat16 g_Wi_lo [HID * KP_BOND];
__device__ __nv_bfloat16 g_Wih_hi[3 * HID * KP_HID];
__device__ __nv_bfloat16 g_Wih_lo[3 * HID * KP_HID];
__device__ __nv_bfloat16 g_Whh_hi[3 * HID * KP_HID];
__device__ __nv_bfloat16 g_Whh_lo[3 * HID * KP_HID];
__device__ __nv_bfloat16 g_Wo_hi [HID * KP_CAT];
__device__ __nv_bfloat16 g_Wo_lo [HID * KP_CAT];

// ================= helpers ======================================================
__device__ __forceinline__ unsigned smem_u32(const void* p) {
    return (unsigned)__cvta_generic_to_shared(p);
}
__device__ __forceinline__ void cp16(unsigned dst, const void* src) {
    asm volatile("cp.async.cg.shared.global [%0], [%1], 16;\n" :: "r"(dst), "l"(src));
}
__device__ __forceinline__ void cp_commit() { asm volatile("cp.async.commit_group;\n"); }
__device__ __forceinline__ void cp_wait0()  { asm volatile("cp.async.wait_group 0;\n"); }
__device__ __forceinline__ void sts_zero16(unsigned dst) {
    asm volatile("st.shared.v4.b32 [%0], {%1,%1,%1,%1};" :: "r"(dst), "r"(0));
}
__device__ __forceinline__ void ldsm_x4(unsigned& r0, unsigned& r1, unsigned& r2,
                                        unsigned& r3, unsigned addr) {
    asm volatile("ldmatrix.sync.aligned.m8n8.x4.shared.b16 {%0,%1,%2,%3}, [%4];"
                 : "=r"(r0), "=r"(r1), "=r"(r2), "=r"(r3) : "r"(addr));
}
__device__ __forceinline__ void mma_bf16(float* c, const unsigned* a, const unsigned* b) {
    asm volatile(
        "mma.sync.aligned.m16n8k16.row.col.f32.bf16.bf16.f32 "
        "{%0,%1,%2,%3},{%4,%5,%6,%7},{%8,%9},{%0,%1,%2,%3};"
        : "+f"(c[0]), "+f"(c[1]), "+f"(c[2]), "+f"(c[3])
        : "r"(a[0]), "r"(a[1]), "r"(a[2]), "r"(a[3]), "r"(b[0]), "r"(b[1]));
}
__device__ __forceinline__ void bf16_split(float v, __nv_bfloat16& hi, __nv_bfloat16& lo) {
    hi = __float2bfloat16_rn(v);
    lo = __float2bfloat16_rn(v - __bfloat162float(hi));
}
__device__ __forceinline__ float sigmoidf1(float x) { return 1.f / (1.f + expf(-x)); }

// ================= bf16x3 TN GEMM (round-9 mainloop; rich epilogue) =============
// C[m,n] = sum_k A[m,k]*B[n,k], A = Ah+Al, B = Bh+Bl (bf16 2-term splits).
// C += Al*Bh + Ah*Bl + Ah*Bh  (fp32 accumulate)
// Epilogue extras:
//   addin (optional): C[m,n] += addin[m,n] for n < addin_lim   (gi fold for r,z gates)
//   Chi/Clo (optional): also write bf16 split of result at stride KPo (fused split)
#define BM 128
#define BN 128
#define BK 32
#define ROWS 40                      // smem row stride in bf16 (32 + 8 pad)
#define BUF_ELEMS (2 * BM * ROWS)    // per buffer, 2 stages = 10240 bf16
#define SMEM_BYTES (4 * BUF_ELEMS * 2)  // 81920 B

__global__ void __launch_bounds__(256, 2)
mma_gemm_bf16x3(const __nv_bfloat16* __restrict__ Ahg, const __nv_bfloat16* __restrict__ Alg,
                const __nv_bfloat16* __restrict__ Bhg, const __nv_bfloat16* __restrict__ Blg,
                const float* __restrict__ bias, const float* __restrict__ mask,
                const float* __restrict__ addin, int addin_lim,
                __nv_bfloat16* __restrict__ Chi, __nv_bfloat16* __restrict__ Clo, int KPo,
                float* __restrict__ C, int M, int N, int KT, int KP, int relu)
{
    extern __shared__ __nv_bfloat16 smem[];
    __nv_bfloat16* Ah = smem;
    __nv_bfloat16* Al = smem + BUF_ELEMS;
    __nv_bfloat16* Bh = smem + 2 * BUF_ELEMS;
    __nv_bfloat16* Bl = smem + 3 * BUF_ELEMS;

    const int tid  = threadIdx.x;
    const int wid  = tid >> 5;
    const int lane = tid & 31;
    const int warp_m = wid & 1;     // 2 warps x 64 rows
    const int warp_n = wid >> 1;    // 4 warps x 32 cols
    const int m0 = blockIdx.y * BM;
    const int n0 = blockIdx.x * BN;
    const int mat = lane >> 3;      // ldmatrix address groups
    const int rw  = lane & 7;

    float acc[4][4][4];
    #pragma unroll
    for (int mi = 0; mi < 4; mi++)
        #pragma unroll
        for (int ni = 0; ni < 4; ni++)
            #pragma unroll
            for (int r = 0; r < 4; r++) acc[mi][ni][r] = 0.f;

    auto load_tile = [&](int kt, int s) {
        const int k0 = kt * BK;
        const int sb = s * BM * ROWS;
        #pragma unroll
        for (int i = 0; i < 2; i++) {
            int idx = tid + i * 256;
            int row = idx >> 2, seg = idx & 3;
            int kc = seg * 8;
            unsigned offA = smem_u32(&Ah[sb + row * ROWS + kc]);
            unsigned offAl = smem_u32(&Al[sb + row * ROWS + kc]);
            unsigned offB = smem_u32(&Bh[sb + row * ROWS + kc]);
            unsigned offBl = smem_u32(&Bl[sb + row * ROWS + kc]);
            int gm = m0 + row, gn = n0 + row;
            if (gm < M) {
                size_t go = (size_t)gm * KP + k0 + kc;
                cp16(offA, Ahg + go);
                cp16(offAl, Alg + go);
            } else { sts_zero16(offA); sts_zero16(offAl); }
            if (gn < N) {
                size_t go = (size_t)gn * KP + k0 + kc;
                cp16(offB, Bhg + go);
                cp16(offBl, Blg + go);
            } else { sts_zero16(offB); sts_zero16(offBl); }
        }
    };

    load_tile(0, 0);
    cp_commit();

    for (int kt = 0; kt < KT; kt++) {
        cp_wait0();
        __syncthreads();
        const int cur = kt & 1;
        if (kt + 1 < KT) load_tile(kt + 1, cur ^ 1);
        cp_commit();
        const int sb = cur * BM * ROWS;

        #pragma unroll
        for (int kk = 0; kk < BK; kk += 16) {
            unsigned ah[4][4], al[4][4];
            #pragma unroll
            for (int mi = 0; mi < 4; mi++) {
                int arow = warp_m * 64 + mi * 16 + ((mat & 1) << 3) + rw;
                int acol = kk + ((mat >> 1) << 3);
                unsigned ad = smem_u32(&Ah[sb + arow * ROWS + acol]);
                ldsm_x4(ah[mi][0], ah[mi][1], ah[mi][2], ah[mi][3], ad);
                unsigned ad2 = smem_u32(&Al[sb + arow * ROWS + acol]);
                ldsm_x4(al[mi][0], al[mi][1], al[mi][2], al[mi][3], ad2);
            }
            unsigned bh[4][2], bl[4][2];
            #pragma unroll
            for (int ni2 = 0; ni2 < 2; ni2++) {
                int brow = warp_n * 32 + ni2 * 16 + ((mat >> 1) << 3) + rw;
                int bcol = kk + ((mat & 1) << 3);
                unsigned r0, r1, r2, r3;
                unsigned bd = smem_u32(&Bh[sb + brow * ROWS + bcol]);
                ldsm_x4(r0, r1, r2, r3, bd);
                bh[ni2*2  ][0] = r0; bh[ni2*2  ][1] = r1;
                bh[ni2*2+1][0] = r2; bh[ni2*2+1][1] = r3;
                unsigned bd2 = smem_u32(&Bl[sb + brow * ROWS + bcol]);
                ldsm_x4(r0, r1, r2, r3, bd2);
                bl[ni2*2  ][0] = r0; bl[ni2*2  ][1] = r1;
                bl[ni2*2+1][0] = r2; bl[ni2*2+1][1] = r3;
            }
            #pragma unroll
            for (int mi = 0; mi < 4; mi++)
                #pragma unroll
                for (int ni = 0; ni < 4; ni++) {
                    mma_bf16(acc[mi][ni], al[mi], bh[ni]);   // lo*hi
                    mma_bf16(acc[mi][ni], ah[mi], bl[ni]);   // hi*lo
                    mma_bf16(acc[mi][ni], ah[mi], bh[ni]);   // hi*hi
                }
        }
        __syncthreads();   // keep load phase and ldmatrix phase separated (round-9 proven)
    }

    // epilogue
    const int g = lane >> 2, t = lane & 3;
    #pragma unroll
    for (int mi = 0; mi < 4; mi++) {
        #pragma unroll
        for (int ni = 0; ni < 4; ni++) {
            int cn = n0 + warp_n * 32 + ni * 8 + 2 * t;
            float b0 = 0.f, b1 = 0.f;
            if (bias) {
                if (cn     < N) b0 = bias[cn];
                if (cn + 1 < N) b1 = bias[cn + 1];
            }
            #pragma unroll
            for (int half = 0; half < 2; half++) {
                int rm = m0 + warp_m * 64 + mi * 16 + g + half * 8;
                if (rm >= M) continue;
                float v0 = acc[mi][ni][half * 2 + 0] + b0;
                float v1 = acc[mi][ni][half * 2 + 1] + b1;
                if (addin && cn + 1 < N && cn < addin_lim) {
                    const float* ap = addin + (size_t)rm * N + cn;
                    v0 += ap[0];
                    v1 += ap[1];
                }
                if (relu) { v0 = fmaxf(v0, 0.f); v1 = fmaxf(v1, 0.f); }
                if (mask) { float mk = mask[rm]; v0 *= mk; v1 *= mk; }
                if (cn + 1 < N) {
                    float2 v = {v0, v1};
                    *(float2*)(C + (size_t)rm * N + cn) = v;
                    if (Chi) {
                        __nv_bfloat16 h0, l0, h1, l1;
                        bf16_split(v0, h0, l0);
                        bf16_split(v1, h1, l1);
                        *(__nv_bfloat162*)(Chi + (size_t)rm * KPo + cn) = __nv_bfloat162(h0, h1);
                        *(__nv_bfloat162*)(Clo + (size_t)rm * KPo + cn) = __nv_bfloat162(l0, l1);
                    }
                } else if (cn < N) {
                    C[(size_t)rm * N + cn] = v0;
                    if (Chi) {
                        __nv_bfloat16 h0, l0;
                        bf16_split(v0, h0, l0);
                        Chi[(size_t)rm * KPo + cn] = h0;
                        Clo[(size_t)rm * KPo + cn] = l0;
                    }
                }
            }
        }
    }
}

// ================= split producers ==============================================
__global__ void split_bf16(const float* __restrict__ src,
                           __nv_bfloat16* __restrict__ hi,
                           __nv_bfloat16* __restrict__ lo,
                           int M, int K, int KP)
{
    int idx = blockIdx.x * blockDim.x + threadIdx.x;
    if (idx >= M * KP) return;
    int m = idx / KP;
    int k = idx - m * KP;
    float v = (k < K) ? src[(size_t)m * K + k] : 0.f;
    __nv_bfloat16 h, l;
    bf16_split(v, h, l);
    hi[idx] = h;
    lo[idx] = l;
}

// fused split of ALL weight matrices in one launch (range dispatch)
#define W1_END (HID * KP_BOND)                       // W_i
#define W2_END (W1_END + 3 * HID * KP_HID)           // W_ih
#define W3_END (W2_END + 3 * HID * KP_HID)           // W_hh
#define W4_END (W3_END + HID * KP_CAT)               // W_o
__global__ void split_weights_all(const float* __restrict__ W_i,
                                  const float* __restrict__ W_ih,
                                  const float* __restrict__ W_hh,
                                  const float* __restrict__ W_o,
                                  __nv_bfloat16* __restrict__ Wi_hi, __nv_bfloat16* __restrict__ Wi_lo,
                                  __nv_bfloat16* __restrict__ Wih_hi, __nv_bfloat16* __restrict__ Wih_lo,
                                  __nv_bfloat16* __restrict__ Whh_hi, __nv_bfloat16* __restrict__ Whh_lo,
                                  __nv_bfloat16* __restrict__ Wo_hi, __nv_bfloat16* __restrict__ Wo_lo)
{
    int idx = blockIdx.x * blockDim.x + threadIdx.x;
    if (idx >= W4_END) return;
    const float* src; __nv_bfloat16 *hi, *lo;
    int off, K, KP;
    if (idx < W1_END)      { src = W_i;  hi = Wi_hi;  lo = Wi_lo;  off = idx;          K = BOND_FDIM; KP = KP_BOND; }
    else if (idx < W2_END) { src = W_ih; hi = Wih_hi; lo = Wih_lo; off = idx - W1_END; K = HID;       KP = KP_HID; }
    else if (idx < W3_END) { src = W_hh; hi = Whh_hi; lo = Whh_lo; off = idx - W2_END; K = HID;       KP = KP_HID; }
    else                   { src = W_o;  hi = Wo_hi;  lo = Wo_lo;  off = idx - W3_END; K = CAT_DIM;   KP = KP_CAT; }
    int m = off / KP;
    int k = off - m * KP;
    float v = (k < K) ? src[(size_t)m * K + k] : 0.f;
    __nv_bfloat16 h, l;
    bf16_split(v, h, l);
    hi[off] = h;
    lo[off] = l;
}

// zero the pad columns [HID, KP_HID) of a bonds x KP_HID split pair
__global__ void zero_pad_h(__nv_bfloat16* __restrict__ hi, __nv_bfloat16* __restrict__ lo)
{
    int idx = blockIdx.x * blockDim.x + threadIdx.x;
    const int PADW = KP_HID - HID;   // 20
    if (idx >= N_BONDS * PADW) return;
    int b = idx / PADW;
    int k = HID + (idx - b * PADW);
    hi[(size_t)b * KP_HID + k] = __float2bfloat16(0.f);
    lo[(size_t)b * KP_HID + k] = __float2bfloat16(0.f);
}

// ================= elementwise ==================================================
__global__ void gather_sum4(const float4* __restrict__ msg,
                            const int* __restrict__ a2b,
                            float4* __restrict__ amsg)
{
    int idx = blockIdx.x * blockDim.x + threadIdx.x;
    if (idx >= N_ATOMS * H4) return;
    int a = idx / H4;
    int j = idx - a * H4;
    const int* nb = a2b + (size_t)a * MAX_NB;
    float4 s = {0.f, 0.f, 0.f, 0.f};
    #pragma unroll
    for (int i = 0; i < MAX_NB; i++) {
        float4 v = msg[(size_t)nb[i] * H4 + j];
        s.x += v.x; s.y += v.y; s.z += v.z; s.w += v.w;
    }
    amsg[idx] = s;
}

// h = amsg[b2a] - msg[b2revb]; writes ONLY the bf16 hi/lo split (padded stride).
__global__ void hpre4_split(const float4* __restrict__ amsg,
                            const float4* __restrict__ msg,
                            const int* __restrict__ b2a,
                            const int* __restrict__ b2revb,
                            __nv_bfloat162* __restrict__ h_hi,
                            __nv_bfloat162* __restrict__ h_lo)
{
    int idx = blockIdx.x * blockDim.x + threadIdx.x;
    if (idx >= N_BONDS * H4) return;
    int b = idx / H4;
    int j = idx - b * H4;
    float4 u = amsg[(size_t)b2a[b] * H4 + j];
    float4 v = msg[(size_t)b2revb[b] * H4 + j];
    float4 o = {u.x - v.x, u.y - v.y, u.z - v.z, u.w - v.w};
    __nv_bfloat16 hx, lx, hy, ly, hz, lz, hw, lw;
    bf16_split(o.x, hx, lx);
    bf16_split(o.y, hy, ly);
    bf16_split(o.z, hz, lz);
    bf16_split(o.w, hw, lw);
    size_t base = (size_t)b * (KP_HID / 2) + j * 2;
    h_hi[base]     = __nv_bfloat162(hx, hy);
    h_hi[base + 1] = __nv_bfloat162(hz, hw);
    h_lo[base]     = __nv_bfloat162(lx, ly);
    h_lo[base + 1] = __nv_bfloat162(lz, lw);
}

// GRU with pre-fused r,z gates: gh columns [0,600) already contain gi+gh (+both biases);
// gh columns [600,900) contain h_n (+b_hh_n); gi read only for the n-gate.
__global__ void gru4(const float4* __restrict__ gi,
                     const float4* __restrict__ gh,
                     const __nv_bfloat162* __restrict__ h_hi,
                     const __nv_bfloat162* __restrict__ h_lo,
                     float4* __restrict__ out)
{
    int idx = blockIdx.x * blockDim.x + threadIdx.x;
    if (idx >= N_BONDS * H4) return;
    int b = idx / H4;
    int j = idx - b * H4;
    if (b == 0) { out[idx] = make_float4(0.f, 0.f, 0.f, 0.f); return; }
    size_t gb = (size_t)b * H34;
    float4 rr  = gh[gb + j];            // i_r + h_r (fused in epilogue)
    float4 zz  = gh[gb + H4 + j];       // i_z + h_z (fused)
    float4 hn4 = gh[gb + 2 * H4 + j];   // h_n only
    float4 in4 = gi[gb + 2 * H4 + j];   // i_n
    // reconstruct h = hi + lo
    size_t hb = (size_t)b * (KP_HID / 2) + j * 2;
    __nv_bfloat162 a0 = h_hi[hb], a1 = h_hi[hb + 1];
    __nv_bfloat162 c0 = h_lo[hb], c1 = h_lo[hb + 1];
    float4 hh;
    hh.x = __bfloat162float(a0.x) + __bfloat162float(c0.x);
    hh.y = __bfloat162float(a0.y) + __bfloat162float(c0.y);
    hh.z = __bfloat162float(a1.x) + __bfloat162float(c1.x);
    hh.w = __bfloat162float(a1.y) + __bfloat162float(c1.y);
    float4 o;
    {
        float r = sigmoidf1(rr.x), z = sigmoidf1(zz.x);
        float n = tanhf(in4.x + r * hn4.x);
        o.x = (1.f - z) * n + z * hh.x;
    }
    {
        float r = sigmoidf1(rr.y), z = sigmoidf1(zz.y);
        float n = tanhf(in4.y + r * hn4.y);
        o.y = (1.f - z) * n + z * hh.y;
    }
    {
        float r = sigmoidf1(rr.z), z = sigmoidf1(zz.z);
        float n = tanhf(in4.z + r * hn4.z);
        o.z = (1.f - z) * n + z * hh.z;
    }
    {
        float r = sigmoidf1(rr.w), z = sigmoidf1(zz.w);
        float n = tanhf(in4.w + r * hn4.w);
        o.w = (1.f - z) * n + z * hh.w;
    }
    out[idx] = o;
}

__global__ void concat_split(const float* __restrict__ f_atoms,
                             const float* __restrict__ amsg,
                             __nv_bfloat16* __restrict__ ain_hi,
                             __nv_bfloat16* __restrict__ ain_lo)
{
    int idx = blockIdx.x * blockDim.x + threadIdx.x;
    if (idx >= N_ATOMS * KP_CAT) return;
    int a = idx / KP_CAT;
    int k = idx - a * KP_CAT;
    float v = 0.f;
    if (k < ATOM_FDIM)      v = f_atoms[(size_t)a * ATOM_FDIM + k];
    else if (k < CAT_DIM)   v = amsg[(size_t)a * HID + (k - ATOM_FDIM)];
    __nv_bfloat16 h, l;
    bf16_split(v, h, l);
    ain_hi[idx] = h;
    ain_lo[idx] = l;
}

// ================= launch ========================================================
static inline dim3 gemm_grid(int M, int N) {
    return dim3((N + BN - 1) / BN, (M + BM - 1) / BM);
}

extern "C" void kernel_launch(void* const* d_in, const int* in_sizes, int n_in,
                              void* d_out, int out_size)
{
    const float* f_atoms = (const float*)d_in[0];
    const float* f_bonds = (const float*)d_in[1];
    const int*   a2b     = (const int*)  d_in[2];
    const int*   b2a     = (const int*)  d_in[3];
    const int*   b2revb  = (const int*)  d_in[4];
    const float* mask    = (const float*)d_in[8];
    const float* W_i     = (const float*)d_in[9];   // [300,147]
    const float* W_ih    = (const float*)d_in[10];  // [900,300]
    const float* W_hh    = (const float*)d_in[11];  // [900,300]
    const float* b_ih    = (const float*)d_in[12];
    const float* b_hh    = (const float*)d_in[13];
    const float* W_o_w   = (const float*)d_in[14];  // [300,433]
    const float* W_o_b   = (const float*)d_in[15];
    float* out = (float*)d_out;

    float *p_inp, *p_gi, *p_msg, *p_gh, *p_amsg;
    __nv_bfloat16 *p_fb_hi, *p_fb_lo, *p_inp_hi, *p_inp_lo, *p_h_hi, *p_h_lo;
    __nv_bfloat16 *p_ain_hi, *p_ain_lo;
    __nv_bfloat16 *p_Wi_hi, *p_Wi_lo, *p_Wih_hi, *p_Wih_lo, *p_Whh_hi, *p_Whh_lo;
    __nv_bfloat16 *p_Wo_hi, *p_Wo_lo;
    cudaGetSymbolAddress((void**)&p_inp,    g_inp);
    cudaGetSymbolAddress((void**)&p_gi,     g_gi);
    cudaGetSymbolAddress((void**)&p_msg,    g_msg);
    cudaGetSymbolAddress((void**)&p_gh,     g_gh);
    cudaGetSymbolAddress((void**)&p_amsg,   g_amsg);
    cudaGetSymbolAddress((void**)&p_fb_hi,  g_fb_hi);
    cudaGetSymbolAddress((void**)&p_fb_lo,  g_fb_lo);
    cudaGetSymbolAddress((void**)&p_inp_hi, g_inp_hi);
    cudaGetSymbolAddress((void**)&p_inp_lo, g_inp_lo);
    cudaGetSymbolAddress((void**)&p_h_hi,   g_h_hi);
    cudaGetSymbolAddress((void**)&p_h_lo,   g_h_lo);
    cudaGetSymbolAddress((void**)&p_ain_hi, g_ain_hi);
    cudaGetSymbolAddress((void**)&p_ain_lo, g_ain_lo);
    cudaGetSymbolAddress((void**)&p_Wi_hi,  g_Wi_hi);
    cudaGetSymbolAddress((void**)&p_Wi_lo,  g_Wi_lo);
    cudaGetSymbolAddress((void**)&p_Wih_hi, g_Wih_hi);
    cudaGetSymbolAddress((void**)&p_Wih_lo, g_Wih_lo);
    cudaGetSymbolAddress((void**)&p_Whh_hi, g_Whh_hi);
    cudaGetSymbolAddress((void**)&p_Whh_lo, g_Whh_lo);
    cudaGetSymbolAddress((void**)&p_Wo_hi,  g_Wo_hi);
    cudaGetSymbolAddress((void**)&p_Wo_lo,  g_Wo_lo);

    static bool attr_set = false;
    if (!attr_set) {
        cudaFuncSetAttribute(mma_gemm_bf16x3,
                             cudaFuncAttributeMaxDynamicSharedMemorySize, SMEM_BYTES);
        attr_set = true;
    }

    const int EW = 256;
    int nb4_grid = (N_BONDS * H4 + EW - 1) / EW;
    int na4_grid = (N_ATOMS * H4 + EW - 1) / EW;
    auto sgrid = [](long n) { return (int)((n + 255) / 256); };

    // 1. split f_bonds
    split_bf16<<<sgrid((long)N_BONDS * KP_BOND), 256>>>(f_bonds, p_fb_hi, p_fb_lo,
                                                        N_BONDS, BOND_FDIM, KP_BOND);
    // 2. split all weights (one fused launch)
    split_weights_all<<<sgrid((long)W4_END), 256>>>(
        W_i, W_ih, W_hh, W_o_w,
        p_Wi_hi, p_Wi_lo, p_Wih_hi, p_Wih_lo,
        p_Whh_hi, p_Whh_lo, p_Wo_hi, p_Wo_lo);
    // 3+4. zero pad columns of h and inp split buffers
    zero_pad_h<<<sgrid((long)N_BONDS * (KP_HID - HID)), 256>>>(p_h_hi, p_h_lo);
    zero_pad_h<<<sgrid((long)N_BONDS * (KP_HID - HID)), 256>>>(p_inp_hi, p_inp_lo);

    // 5. inp = f_bonds @ W_i^T   [90000,300] KP=160 (KT=5); fused bf16 split output
    mma_gemm_bf16x3<<<gemm_grid(N_BONDS, HID), 256, SMEM_BYTES>>>(
        p_fb_hi, p_fb_lo, p_Wi_hi, p_Wi_lo, nullptr, nullptr,
        nullptr, 0, p_inp_hi, p_inp_lo, KP_HID,
        p_inp, N_BONDS, HID, KP_BOND / BK, KP_BOND, 0);

    // 6. gi = inp @ W_ih^T + b_ih   [90000,900] KP=320 (KT=10)
    mma_gemm_bf16x3<<<gemm_grid(N_BONDS, 3 * HID), 256, SMEM_BYTES>>>(
        p_inp_hi, p_inp_lo, p_Wih_hi, p_Wih_lo, b_ih, nullptr,
        nullptr, 0, nullptr, nullptr, 0,
        p_gi, N_BONDS, 3 * HID, KP_HID / BK, KP_HID, 0);

    const float* msg_src = p_inp;
    for (int it = 0; it < DEPTH - 1; it++) {
        gather_sum4<<<na4_grid, EW>>>((const float4*)msg_src, a2b, (float4*)p_amsg);
        hpre4_split<<<nb4_grid, EW>>>((const float4*)p_amsg, (const float4*)msg_src,
                                      b2a, b2revb,
                                      (__nv_bfloat162*)p_h_hi, (__nv_bfloat162*)p_h_lo);
        // gh = h @ W_hh^T + b_hh, with gi folded into r,z columns (< 600)
        mma_gemm_bf16x3<<<gemm_grid(N_BONDS, 3 * HID), 256, SMEM_BYTES>>>(
            p_h_hi, p_h_lo, p_Whh_hi, p_Whh_lo, b_hh, nullptr,
            p_gi, 2 * HID, nullptr, nullptr, 0,
            p_gh, N_BONDS, 3 * HID, KP_HID / BK, KP_HID, 0);
        gru4<<<nb4_grid, EW>>>((const float4*)p_gi, (const float4*)p_gh,
                               (const __nv_bfloat162*)p_h_hi,
                               (const __nv_bfloat162*)p_h_lo, (float4*)p_msg);
        msg_src = p_msg;
    }

    gather_sum4<<<na4_grid, EW>>>((const float4*)msg_src, a2b, (float4*)p_amsg);
    concat_split<<<sgrid((long)N_ATOMS * KP_CAT), 256>>>(f_atoms, p_amsg,
                                                         p_ain_hi, p_ain_lo);
    // out = relu(ain @ W_o_w^T + W_o_b) * mask   [40000,300] KP=448 (KT=14)
    mma_gemm_bf16x3<<<gemm_grid(N_ATOMS, HID), 256, SMEM_BYTES>>>(
        p_ain_hi, p_ain_lo, p_Wo_hi, p_Wo_lo, W_o_b, mask,
        nullptr, 0, nullptr, nullptr, 0,
        out, N_ATOMS, HID, KP_CAT / BK, KP_CAT, 1);
}

// round 12
// speedup vs baseline: 1.0638x; 1.0638x over previous
#include <cuda_runtime.h>
#include <cuda_bf16.h>
#include <math.h>
#include <stdint.h>

#define N_ATOMS 40000
#define N_BONDS 90000
#define MAX_NB 6
#define ATOM_FDIM 133
#define BOND_FDIM 147
#define HID 300
#define DEPTH 6
#define CAT_DIM (ATOM_FDIM + HID)   // 433

#define H4   (HID / 4)              // 75
#define H34  (3 * HID / 4)          // 225

// padded K strides (multiples of 32) for bf16 split operands
#define KP_BOND 160                 // 147 -> 160
#define KP_HID  320                 // 300 -> 320
#define KP_CAT  448                 // 433 -> 448

// ---------------- scratch (device globals; no cudaMalloc allowed) -------------
__device__ float g_inp [N_BONDS * HID];
__device__ float g_gi  [N_BONDS * 3 * HID];
__device__ float g_msg [N_BONDS * HID];
__device__ float g_gh  [N_BONDS * 3 * HID];
__device__ float g_amsg[N_ATOMS * HID];

__device__ __nv_bfloat16 g_fb_hi [N_BONDS * KP_BOND];
__device__ __nv_bfloat16 g_fb_lo [N_BONDS * KP_BOND];
__device__ __nv_bfloat16 g_inp_hi[N_BONDS * KP_HID];
__device__ __nv_bfloat16 g_inp_lo[N_BONDS * KP_HID];
__device__ __nv_bfloat16 g_h_hi  [N_BONDS * KP_HID];
__device__ __nv_bfloat16 g_h_lo  [N_BONDS * KP_HID];
__device__ __nv_bfloat16 g_ain_hi[N_ATOMS * KP_CAT];
__device__ __nv_bfloat16 g_ain_lo[N_ATOMS * KP_CAT];
__device__ __nv_bfloat16 g_Wi_hi [HID * KP_BOND];
__device__ __nv_bfloat16 g_Wi_lo [HID * KP_BOND];
__device__ __nv_bfloat16 g_Wih_hi[3 * HID * KP_HID];
__device__ __nv_bfloat16 g_Wih_lo[3 * HID * KP_HID];
__device__ __nv_bfloat16 g_Whh_hi[3 * HID * KP_HID];
__device__ __nv_bfloat16 g_Whh_lo[3 * HID * KP_HID];
__device__ __nv_bfloat16 g_Wo_hi [HID * KP_CAT];
__device__ __nv_bfloat16 g_Wo_lo [HID * KP_CAT];

// ================= helpers ======================================================
__device__ __forceinline__ unsigned smem_u32(const void* p) {
    return (unsigned)__cvta_generic_to_shared(p);
}
__device__ __forceinline__ void cp16(unsigned dst, const void* src) {
    asm volatile("cp.async.cg.shared.global [%0], [%1], 16;\n" :: "r"(dst), "l"(src));
}
__device__ __forceinline__ void cp_commit() { asm volatile("cp.async.commit_group;\n"); }
__device__ __forceinline__ void cp_wait0()  { asm volatile("cp.async.wait_group 0;\n"); }
__device__ __forceinline__ void sts_zero16(unsigned dst) {
    asm volatile("st.shared.v4.b32 [%0], {%1,%1,%1,%1};" :: "r"(dst), "r"(0));
}
__device__ __forceinline__ void ldsm_x4(unsigned& r0, unsigned& r1, unsigned& r2,
                                        unsigned& r3, unsigned addr) {
    asm volatile("ldmatrix.sync.aligned.m8n8.x4.shared.b16 {%0,%1,%2,%3}, [%4];"
                 : "=r"(r0), "=r"(r1), "=r"(r2), "=r"(r3) : "r"(addr));
}
__device__ __forceinline__ void mma_bf16(float* c, const unsigned* a, const unsigned* b) {
    asm volatile(
        "mma.sync.aligned.m16n8k16.row.col.f32.bf16.bf16.f32 "
        "{%0,%1,%2,%3},{%4,%5,%6,%7},{%8,%9},{%0,%1,%2,%3};"
        : "+f"(c[0]), "+f"(c[1]), "+f"(c[2]), "+f"(c[3])
        : "r"(a[0]), "r"(a[1]), "r"(a[2]), "r"(a[3]), "r"(b[0]), "r"(b[1]));
}
__device__ __forceinline__ void bf16_split(float v, __nv_bfloat16& hi, __nv_bfloat16& lo) {
    hi = __float2bfloat16_rn(v);
    lo = __float2bfloat16_rn(v - __bfloat162float(hi));
}
__device__ __forceinline__ float sigmoidf1(float x) { return 1.f / (1.f + expf(-x)); }

// ================= bf16x3 TN GEMM (round-9 signature; 3-pass MMA; no trail bar) ==
// C[m,n] = sum_k A[m,k]*B[n,k], A = Ah+Al, B = Bh+Bl (bf16 2-term splits).
// C += Al*Bh + Ah*Bl + Ah*Bh  (fp32 accumulate; per-acc order preserved)
#define BM 128
#define BN 128
#define BK 32
#define ROWS 40                      // smem row stride in bf16 (32 + 8 pad)
#define BUF_ELEMS (2 * BM * ROWS)    // per buffer, 2 stages = 10240 bf16
#define SMEM_BYTES (4 * BUF_ELEMS * 2)  // 81920 B

__global__ void __launch_bounds__(256, 2)
mma_gemm_bf16x3(const __nv_bfloat16* __restrict__ Ahg, const __nv_bfloat16* __restrict__ Alg,
                const __nv_bfloat16* __restrict__ Bhg, const __nv_bfloat16* __restrict__ Blg,
                const float* __restrict__ bias, const float* __restrict__ mask,
                float* __restrict__ C, int M, int N, int KT, int KP, int relu)
{
    extern __shared__ __nv_bfloat16 smem[];
    __nv_bfloat16* Ah = smem;
    __nv_bfloat16* Al = smem + BUF_ELEMS;
    __nv_bfloat16* Bh = smem + 2 * BUF_ELEMS;
    __nv_bfloat16* Bl = smem + 3 * BUF_ELEMS;

    const int tid  = threadIdx.x;
    const int wid  = tid >> 5;
    const int lane = tid & 31;
    const int warp_m = wid & 1;     // 2 warps x 64 rows
    const int warp_n = wid >> 1;    // 4 warps x 32 cols
    const int m0 = blockIdx.y * BM;
    const int n0 = blockIdx.x * BN;
    const int mat = lane >> 3;      // ldmatrix address groups
    const int rw  = lane & 7;

    float acc[4][4][4];
    #pragma unroll
    for (int mi = 0; mi < 4; mi++)
        #pragma unroll
        for (int ni = 0; ni < 4; ni++)
            #pragma unroll
            for (int r = 0; r < 4; r++) acc[mi][ni][r] = 0.f;

    auto load_tile = [&](int kt, int s) {
        const int k0 = kt * BK;
        const int sb = s * BM * ROWS;
        #pragma unroll
        for (int i = 0; i < 2; i++) {
            int idx = tid + i * 256;
            int row = idx >> 2, seg = idx & 3;
            int kc = seg * 8;
            unsigned offA = smem_u32(&Ah[sb + row * ROWS + kc]);
            unsigned offAl = smem_u32(&Al[sb + row * ROWS + kc]);
            unsigned offB = smem_u32(&Bh[sb + row * ROWS + kc]);
            unsigned offBl = smem_u32(&Bl[sb + row * ROWS + kc]);
            int gm = m0 + row, gn = n0 + row;
            if (gm < M) {
                size_t go = (size_t)gm * KP + k0 + kc;
                cp16(offA, Ahg + go);
                cp16(offAl, Alg + go);
            } else { sts_zero16(offA); sts_zero16(offAl); }
            if (gn < N) {
                size_t go = (size_t)gn * KP + k0 + kc;
                cp16(offB, Bhg + go);
                cp16(offBl, Blg + go);
            } else { sts_zero16(offB); sts_zero16(offBl); }
        }
    };

    load_tile(0, 0);
    cp_commit();

    for (int kt = 0; kt < KT; kt++) {
        cp_wait0();
        __syncthreads();     // orders: tile kt resident AND prior MMA phase done
        const int cur = kt & 1;
        if (kt + 1 < KT) load_tile(kt + 1, cur ^ 1);
        cp_commit();
        const int sb = cur * BM * ROWS;

        #pragma unroll
        for (int kk = 0; kk < BK; kk += 16) {
            unsigned ah[4][4], al[4][4];
            #pragma unroll
            for (int mi = 0; mi < 4; mi++) {
                int arow = warp_m * 64 + mi * 16 + ((mat & 1) << 3) + rw;
                int acol = kk + ((mat >> 1) << 3);
                unsigned ad = smem_u32(&Ah[sb + arow * ROWS + acol]);
                ldsm_x4(ah[mi][0], ah[mi][1], ah[mi][2], ah[mi][3], ad);
                unsigned ad2 = smem_u32(&Al[sb + arow * ROWS + acol]);
                ldsm_x4(al[mi][0], al[mi][1], al[mi][2], al[mi][3], ad2);
            }
            unsigned bh[4][2], bl[4][2];
            #pragma unroll
            for (int ni2 = 0; ni2 < 2; ni2++) {
                int brow = warp_n * 32 + ni2 * 16 + ((mat >> 1) << 3) + rw;
                int bcol = kk + ((mat & 1) << 3);
                unsigned r0, r1, r2, r3;
                unsigned bd = smem_u32(&Bh[sb + brow * ROWS + bcol]);
                ldsm_x4(r0, r1, r2, r3, bd);
                bh[ni2*2  ][0] = r0; bh[ni2*2  ][1] = r1;
                bh[ni2*2+1][0] = r2; bh[ni2*2+1][1] = r3;
                unsigned bd2 = smem_u32(&Bl[sb + brow * ROWS + bcol]);
                ldsm_x4(r0, r1, r2, r3, bd2);
                bl[ni2*2  ][0] = r0; bl[ni2*2  ][1] = r1;
                bl[ni2*2+1][0] = r2; bl[ni2*2+1][1] = r3;
            }
            // 3 passes of 16 independent MMAs each; per-accumulator order unchanged
            #pragma unroll
            for (int mi = 0; mi < 4; mi++)
                #pragma unroll
                for (int ni = 0; ni < 4; ni++)
                    mma_bf16(acc[mi][ni], al[mi], bh[ni]);   // lo*hi
            #pragma unroll
            for (int mi = 0; mi < 4; mi++)
                #pragma unroll
                for (int ni = 0; ni < 4; ni++)
                    mma_bf16(acc[mi][ni], ah[mi], bl[ni]);   // hi*lo
            #pragma unroll
            for (int mi = 0; mi < 4; mi++)
                #pragma unroll
                for (int ni = 0; ni < 4; ni++)
                    mma_bf16(acc[mi][ni], ah[mi], bh[ni]);   // hi*hi
        }
        // no trailing barrier: next iteration's leading barrier covers the hazard
        // (buffer s is only overwritten by load_tile(kt+2), issued after that barrier)
    }

    // epilogue (round-9 minimal form)
    const int g = lane >> 2, t = lane & 3;
    #pragma unroll
    for (int mi = 0; mi < 4; mi++) {
        #pragma unroll
        for (int ni = 0; ni < 4; ni++) {
            int cn = n0 + warp_n * 32 + ni * 8 + 2 * t;
            float b0 = 0.f, b1 = 0.f;
            if (bias) {
                if (cn     < N) b0 = bias[cn];
                if (cn + 1 < N) b1 = bias[cn + 1];
            }
            #pragma unroll
            for (int half = 0; half < 2; half++) {
                int rm = m0 + warp_m * 64 + mi * 16 + g + half * 8;
                if (rm >= M) continue;
                float v0 = acc[mi][ni][half * 2 + 0] + b0;
                float v1 = acc[mi][ni][half * 2 + 1] + b1;
                if (relu) { v0 = fmaxf(v0, 0.f); v1 = fmaxf(v1, 0.f); }
                if (mask) { float mk = mask[rm]; v0 *= mk; v1 *= mk; }
                if (cn + 1 < N) {
                    float2 v = {v0, v1};
                    *(float2*)(C + (size_t)rm * N + cn) = v;
                } else if (cn < N) {
                    C[(size_t)rm * N + cn] = v0;
                }
            }
        }
    }
}

// ================= split producers ==============================================
__global__ void split_bf16(const float* __restrict__ src,
                           __nv_bfloat16* __restrict__ hi,
                           __nv_bfloat16* __restrict__ lo,
                           int M, int K, int KP)
{
    int idx = blockIdx.x * blockDim.x + threadIdx.x;
    if (idx >= M * KP) return;
    int m = idx / KP;
    int k = idx - m * KP;
    float v = (k < K) ? src[(size_t)m * K + k] : 0.f;
    __nv_bfloat16 h, l;
    bf16_split(v, h, l);
    hi[idx] = h;
    lo[idx] = l;
}

// fused split of ALL weight matrices in one launch (range dispatch)
#define W1_END (HID * KP_BOND)                       // W_i
#define W2_END (W1_END + 3 * HID * KP_HID)           // W_ih
#define W3_END (W2_END + 3 * HID * KP_HID)           // W_hh
#define W4_END (W3_END + HID * KP_CAT)               // W_o
__global__ void split_weights_all(const float* __restrict__ W_i,
                                  const float* __restrict__ W_ih,
                                  const float* __restrict__ W_hh,
                                  const float* __restrict__ W_o,
                                  __nv_bfloat16* __restrict__ Wi_hi, __nv_bfloat16* __restrict__ Wi_lo,
                                  __nv_bfloat16* __restrict__ Wih_hi, __nv_bfloat16* __restrict__ Wih_lo,
                                  __nv_bfloat16* __restrict__ Whh_hi, __nv_bfloat16* __restrict__ Whh_lo,
                                  __nv_bfloat16* __restrict__ Wo_hi, __nv_bfloat16* __restrict__ Wo_lo)
{
    int idx = blockIdx.x * blockDim.x + threadIdx.x;
    if (idx >= W4_END) return;
    const float* src; __nv_bfloat16 *hi, *lo;
    int off, K, KP;
    if (idx < W1_END)      { src = W_i;  hi = Wi_hi;  lo = Wi_lo;  off = idx;          K = BOND_FDIM; KP = KP_BOND; }
    else if (idx < W2_END) { src = W_ih; hi = Wih_hi; lo = Wih_lo; off = idx - W1_END; K = HID;       KP = KP_HID; }
    else if (idx < W3_END) { src = W_hh; hi = Whh_hi; lo = Whh_lo; off = idx - W2_END; K = HID;       KP = KP_HID; }
    else                   { src = W_o;  hi = Wo_hi;  lo = Wo_lo;  off = idx - W3_END; K = CAT_DIM;   KP = KP_CAT; }
    int m = off / KP;
    int k = off - m * KP;
    float v = (k < K) ? src[(size_t)m * K + k] : 0.f;
    __nv_bfloat16 h, l;
    bf16_split(v, h, l);
    hi[off] = h;
    lo[off] = l;
}

// zero the pad columns [HID, KP_HID) of a bonds x KP_HID split pair
__global__ void zero_pad_h(__nv_bfloat16* __restrict__ hi, __nv_bfloat16* __restrict__ lo)
{
    int idx = blockIdx.x * blockDim.x + threadIdx.x;
    const int PADW = KP_HID - HID;   // 20
    if (idx >= N_BONDS * PADW) return;
    int b = idx / PADW;
    int k = HID + (idx - b * PADW);
    hi[(size_t)b * KP_HID + k] = __float2bfloat16(0.f);
    lo[(size_t)b * KP_HID + k] = __float2bfloat16(0.f);
}

// ================= elementwise ==================================================
__global__ void gather_sum4(const float4* __restrict__ msg,
                            const int* __restrict__ a2b,
                            float4* __restrict__ amsg)
{
    int idx = blockIdx.x * blockDim.x + threadIdx.x;
    if (idx >= N_ATOMS * H4) return;
    int a = idx / H4;
    int j = idx - a * H4;
    const int* nb = a2b + (size_t)a * MAX_NB;
    float4 s = {0.f, 0.f, 0.f, 0.f};
    #pragma unroll
    for (int i = 0; i < MAX_NB; i++) {
        float4 v = msg[(size_t)nb[i] * H4 + j];
        s.x += v.x; s.y += v.y; s.z += v.z; s.w += v.w;
    }
    amsg[idx] = s;
}

// h = amsg[b2a] - msg[b2revb]; writes ONLY the bf16 hi/lo split (padded stride).
__global__ void hpre4_split(const float4* __restrict__ amsg,
                            const float4* __restrict__ msg,
                            const int* __restrict__ b2a,
                            const int* __restrict__ b2revb,
                            __nv_bfloat162* __restrict__ h_hi,
                            __nv_bfloat162* __restrict__ h_lo)
{
    int idx = blockIdx.x * blockDim.x + threadIdx.x;
    if (idx >= N_BONDS * H4) return;
    int b = idx / H4;
    int j = idx - b * H4;
    float4 u = amsg[(size_t)b2a[b] * H4 + j];
    float4 v = msg[(size_t)b2revb[b] * H4 + j];
    float4 o = {u.x - v.x, u.y - v.y, u.z - v.z, u.w - v.w};
    __nv_bfloat16 hx, lx, hy, ly, hz, lz, hw, lw;
    bf16_split(o.x, hx, lx);
    bf16_split(o.y, hy, ly);
    bf16_split(o.z, hz, lz);
    bf16_split(o.w, hw, lw);
    size_t base = (size_t)b * (KP_HID / 2) + j * 2;
    h_hi[base]     = __nv_bfloat162(hx, hy);
    h_hi[base + 1] = __nv_bfloat162(hz, hw);
    h_lo[base]     = __nv_bfloat162(lx, ly);
    h_lo[base + 1] = __nv_bfloat162(lz, lw);
}

// GRU; h reconstructed as hi+lo (exact operand the GEMM consumed)
__global__ void gru4(const float4* __restrict__ gi,
                     const float4* __restrict__ gh,
                     const __nv_bfloat162* __restrict__ h_hi,
                     const __nv_bfloat162* __restrict__ h_lo,
                     float4* __restrict__ out)
{
    int idx = blockIdx.x * blockDim.x + threadIdx.x;
    if (idx >= N_BONDS * H4) return;
    int b = idx / H4;
    int j = idx - b * H4;
    if (b == 0) { out[idx] = make_float4(0.f, 0.f, 0.f, 0.f); return; }
    size_t gb = (size_t)b * H34;
    float4 ir = gi[gb + j], iz = gi[gb + H4 + j], in4 = gi[gb + 2 * H4 + j];
    float4 hr = gh[gb + j], hz = gh[gb + H4 + j], hn4 = gh[gb + 2 * H4 + j];
    size_t hb = (size_t)b * (KP_HID / 2) + j * 2;
    __nv_bfloat162 a0 = h_hi[hb], a1 = h_hi[hb + 1];
    __nv_bfloat162 c0 = h_lo[hb], c1 = h_lo[hb + 1];
    float4 hh;
    hh.x = __bfloat162float(a0.x) + __bfloat162float(c0.x);
    hh.y = __bfloat162float(a0.y) + __bfloat162float(c0.y);
    hh.z = __bfloat162float(a1.x) + __bfloat162float(c1.x);
    hh.w = __bfloat162float(a1.y) + __bfloat162float(c1.y);
    float4 o;
    {
        float r = sigmoidf1(ir.x + hr.x), z = sigmoidf1(iz.x + hz.x);
        float n = tanhf(in4.x + r * hn4.x);
        o.x = (1.f - z) * n + z * hh.x;
    }
    {
        float r = sigmoidf1(ir.y + hr.y), z = sigmoidf1(iz.y + hz.y);
        float n = tanhf(in4.y + r * hn4.y);
        o.y = (1.f - z) * n + z * hh.y;
    }
    {
        float r = sigmoidf1(ir.z + hr.z), z = sigmoidf1(iz.z + hz.z);
        float n = tanhf(in4.z + r * hn4.z);
        o.z = (1.f - z) * n + z * hh.z;
    }
    {
        float r = sigmoidf1(ir.w + hr.w), z = sigmoidf1(iz.w + hz.w);
        float n = tanhf(in4.w + r * hn4.w);
        o.w = (1.f - z) * n + z * hh.w;
    }
    out[idx] = o;
}

__global__ void concat_split(const float* __restrict__ f_atoms,
                             const float* __restrict__ amsg,
                             __nv_bfloat16* __restrict__ ain_hi,
                             __nv_bfloat16* __restrict__ ain_lo)
{
    int idx = blockIdx.x * blockDim.x + threadIdx.x;
    if (idx >= N_ATOMS * KP_CAT) return;
    int a = idx / KP_CAT;
    int k = idx - a * KP_CAT;
    float v = 0.f;
    if (k < ATOM_FDIM)      v = f_atoms[(size_t)a * ATOM_FDIM + k];
    else if (k < CAT_DIM)   v = amsg[(size_t)a * HID + (k - ATOM_FDIM)];
    __nv_bfloat16 h, l;
    bf16_split(v, h, l);
    ain_hi[idx] = h;
    ain_lo[idx] = l;
}

// ================= launch ========================================================
static inline dim3 gemm_grid(int M, int N) {
    return dim3((N + BN - 1) / BN, (M + BM - 1) / BM);
}

extern "C" void kernel_launch(void* const* d_in, const int* in_sizes, int n_in,
                              void* d_out, int out_size)
{
    const float* f_atoms = (const float*)d_in[0];
    const float* f_bonds = (const float*)d_in[1];
    const int*   a2b     = (const int*)  d_in[2];
    const int*   b2a     = (const int*)  d_in[3];
    const int*   b2revb  = (const int*)  d_in[4];
    const float* mask    = (const float*)d_in[8];
    const float* W_i     = (const float*)d_in[9];   // [300,147]
    const float* W_ih    = (const float*)d_in[10];  // [900,300]
    const float* W_hh    = (const float*)d_in[11];  // [900,300]
    const float* b_ih    = (const float*)d_in[12];
    const float* b_hh    = (const float*)d_in[13];
    const float* W_o_w   = (const float*)d_in[14];  // [300,433]
    const float* W_o_b   = (const float*)d_in[15];
    float* out = (float*)d_out;

    float *p_inp, *p_gi, *p_msg, *p_gh, *p_amsg;
    __nv_bfloat16 *p_fb_hi, *p_fb_lo, *p_inp_hi, *p_inp_lo, *p_h_hi, *p_h_lo;
    __nv_bfloat16 *p_ain_hi, *p_ain_lo;
    __nv_bfloat16 *p_Wi_hi, *p_Wi_lo, *p_Wih_hi, *p_Wih_lo, *p_Whh_hi, *p_Whh_lo;
    __nv_bfloat16 *p_Wo_hi, *p_Wo_lo;
    cudaGetSymbolAddress((void**)&p_inp,    g_inp);
    cudaGetSymbolAddress((void**)&p_gi,     g_gi);
    cudaGetSymbolAddress((void**)&p_msg,    g_msg);
    cudaGetSymbolAddress((void**)&p_gh,     g_gh);
    cudaGetSymbolAddress((void**)&p_amsg,   g_amsg);
    cudaGetSymbolAddress((void**)&p_fb_hi,  g_fb_hi);
    cudaGetSymbolAddress((void**)&p_fb_lo,  g_fb_lo);
    cudaGetSymbolAddress((void**)&p_inp_hi, g_inp_hi);
    cudaGetSymbolAddress((void**)&p_inp_lo, g_inp_lo);
    cudaGetSymbolAddress((void**)&p_h_hi,   g_h_hi);
    cudaGetSymbolAddress((void**)&p_h_lo,   g_h_lo);
    cudaGetSymbolAddress((void**)&p_ain_hi, g_ain_hi);
    cudaGetSymbolAddress((void**)&p_ain_lo, g_ain_lo);
    cudaGetSymbolAddress((void**)&p_Wi_hi,  g_Wi_hi);
    cudaGetSymbolAddress((void**)&p_Wi_lo,  g_Wi_lo);
    cudaGetSymbolAddress((void**)&p_Wih_hi, g_Wih_hi);
    cudaGetSymbolAddress((void**)&p_Wih_lo, g_Wih_lo);
    cudaGetSymbolAddress((void**)&p_Whh_hi, g_Whh_hi);
    cudaGetSymbolAddress((void**)&p_Whh_lo, g_Whh_lo);
    cudaGetSymbolAddress((void**)&p_Wo_hi,  g_Wo_hi);
    cudaGetSymbolAddress((void**)&p_Wo_lo,  g_Wo_lo);

    static bool attr_set = false;
    if (!attr_set) {
        cudaFuncSetAttribute(mma_gemm_bf16x3,
                             cudaFuncAttributeMaxDynamicSharedMemorySize, SMEM_BYTES);
        attr_set = true;
    }

    const int EW = 256;
    int nb4_grid = (N_BONDS * H4 + EW - 1) / EW;
    int na4_grid = (N_ATOMS * H4 + EW - 1) / EW;
    auto sgrid = [](long n) { return (int)((n + 255) / 256); };

    // Launch order arranged so ncu's "-s 5 -c 1" captures launch #6 = the gi GEMM.
    // 1. split f_bonds
    split_bf16<<<sgrid((long)N_BONDS * KP_BOND), 256>>>(f_bonds, p_fb_hi, p_fb_lo,
                                                        N_BONDS, BOND_FDIM, KP_BOND);
    // 2. split all weights (one fused launch)
    split_weights_all<<<sgrid((long)W4_END), 256>>>(
        W_i, W_ih, W_hh, W_o_w,
        p_Wi_hi, p_Wi_lo, p_Wih_hi, p_Wih_lo,
        p_Whh_hi, p_Whh_lo, p_Wo_hi, p_Wo_lo);
    // 3. zero h pad columns
    zero_pad_h<<<sgrid((long)N_BONDS * (KP_HID - HID)), 256>>>(p_h_hi, p_h_lo);

    // 4. inp = f_bonds @ W_i^T         [90000,300] KP=160 (KT=5)
    mma_gemm_bf16x3<<<gemm_grid(N_BONDS, HID), 256, SMEM_BYTES>>>(
        p_fb_hi, p_fb_lo, p_Wi_hi, p_Wi_lo, nullptr, nullptr,
        p_inp, N_BONDS, HID, KP_BOND / BK, KP_BOND, 0);

    // 5. split inp
    split_bf16<<<sgrid((long)N_BONDS * KP_HID), 256>>>(p_inp, p_inp_hi, p_inp_lo,
                                                       N_BONDS, HID, KP_HID);

    // 6. gi = inp @ W_ih^T + b_ih      [90000,900] KP=320 (KT=10)  <- ncu target
    mma_gemm_bf16x3<<<gemm_grid(N_BONDS, 3 * HID), 256, SMEM_BYTES>>>(
        p_inp_hi, p_inp_lo, p_Wih_hi, p_Wih_lo, b_ih, nullptr,
        p_gi, N_BONDS, 3 * HID, KP_HID / BK, KP_HID, 0);

    const float* msg_src = p_inp;
    for (int it = 0; it < DEPTH - 1; it++) {
        gather_sum4<<<na4_grid, EW>>>((const float4*)msg_src, a2b, (float4*)p_amsg);
        hpre4_split<<<nb4_grid, EW>>>((const float4*)p_amsg, (const float4*)msg_src,
                                      b2a, b2revb,
                                      (__nv_bfloat162*)p_h_hi, (__nv_bfloat162*)p_h_lo);
        // gh = h @ W_hh^T + b_hh       [90000,900] K=300
        mma_gemm_bf16x3<<<gemm_grid(N_BONDS, 3 * HID), 256, SMEM_BYTES>>>(
            p_h_hi, p_h_lo, p_Whh_hi, p_Whh_lo, b_hh, nullptr,
            p_gh, N_BONDS, 3 * HID, KP_HID / BK, KP_HID, 0);
        gru4<<<nb4_grid, EW>>>((const float4*)p_gi, (const float4*)p_gh,
                               (const __nv_bfloat162*)p_h_hi,
                               (const __nv_bfloat162*)p_h_lo, (float4*)p_msg);
        msg_src = p_msg;
    }

    gather_sum4<<<na4_grid, EW>>>((const float4*)msg_src, a2b, (float4*)p_amsg);
    concat_split<<<sgrid((long)N_ATOMS * KP_CAT), 256>>>(f_atoms, p_amsg,
                                                         p_ain_hi, p_ain_lo);
    // out = relu(ain @ W_o_w^T + W_o_b) * mask   [40000,300] KP=448 (KT=14)
    mma_gemm_bf16x3<<<gemm_grid(N_ATOMS, HID), 256, SMEM_BYTES>>>(
        p_ain_hi, p_ain_lo, p_Wo_hi, p_Wo_lo, W_o_b, mask,
        out, N_ATOMS, HID, KP_CAT / BK, KP_CAT, 1);
}

// round 13
// speedup vs baseline: 1.0677x; 1.0037x over previous
#include <cuda_runtime.h>
#include <cuda_bf16.h>
#include <math.h>
#include <stdint.h>

#define N_ATOMS 40000
#define N_BONDS 90000
#define MAX_NB 6
#define ATOM_FDIM 133
#define BOND_FDIM 147
#define HID 300
#define DEPTH 6
#define CAT_DIM (ATOM_FDIM + HID)   // 433

#define H4   (HID / 4)              // 75
#define H34  (3 * HID / 4)          // 225

// padded K strides (multiples of 32) for bf16 split operands
#define KP_BOND 160                 // 147 -> 160
#define KP_HID  320                 // 300 -> 320
#define KP_CAT  448                 // 433 -> 448

// ---------------- scratch (device globals; no cudaMalloc allowed) -------------
__device__ float g_inp [N_BONDS * HID];
__device__ float g_gi  [N_BONDS * 3 * HID];
__device__ float g_msg [N_BONDS * HID];
__device__ float g_gh  [N_BONDS * 3 * HID];
__device__ float g_amsg[N_ATOMS * HID];

__device__ __nv_bfloat16 g_fb_hi [N_BONDS * KP_BOND];
__device__ __nv_bfloat16 g_fb_lo [N_BONDS * KP_BOND];
__device__ __nv_bfloat16 g_inp_hi[N_BONDS * KP_HID];
__device__ __nv_bfloat16 g_inp_lo[N_BONDS * KP_HID];
__device__ __nv_bfloat16 g_h_hi  [N_BONDS * KP_HID];
__device__ __nv_bfloat16 g_h_lo  [N_BONDS * KP_HID];
__device__ __nv_bfloat16 g_ain_hi[N_ATOMS * KP_CAT];
__device__ __nv_bfloat16 g_ain_lo[N_ATOMS * KP_CAT];
__device__ __nv_bfloat16 g_Wi_hi [HID * KP_BOND];
__device__ __nv_bfloat16 g_Wi_lo [HID * KP_BOND];
__device__ __nv_bfloat16 g_Wih_hi[3 * HID * KP_HID];
__device__ __nv_bfloat16 g_Wih_lo[3 * HID * KP_HID];
__device__ __nv_bfloat16 g_Whh_hi[3 * HID * KP_HID];
__device__ __nv_bfloat16 g_Whh_lo[3 * HID * KP_HID];
__device__ __nv_bfloat16 g_Wo_hi [HID * KP_CAT];
__device__ __nv_bfloat16 g_Wo_lo [HID * KP_CAT];

// ================= helpers ======================================================
__device__ __forceinline__ unsigned smem_u32(const void* p) {
    return (unsigned)__cvta_generic_to_shared(p);
}
__device__ __forceinline__ void cp16(unsigned dst, const void* src) {
    asm volatile("cp.async.cg.shared.global [%0], [%1], 16;\n" :: "r"(dst), "l"(src));
}
__device__ __forceinline__ void cp_commit() { asm volatile("cp.async.commit_group;\n"); }
__device__ __forceinline__ void cp_wait0()  { asm volatile("cp.async.wait_group 0;\n"); }
__device__ __forceinline__ void sts_zero16(unsigned dst) {
    asm volatile("st.shared.v4.b32 [%0], {%1,%1,%1,%1};" :: "r"(dst), "r"(0));
}
__device__ __forceinline__ void ldsm_x4(unsigned& r0, unsigned& r1, unsigned& r2,
                                        unsigned& r3, unsigned addr) {
    asm volatile("ldmatrix.sync.aligned.m8n8.x4.shared.b16 {%0,%1,%2,%3}, [%4];"
                 : "=r"(r0), "=r"(r1), "=r"(r2), "=r"(r3) : "r"(addr));
}
__device__ __forceinline__ void mma_bf16(float* c, const unsigned* a, const unsigned* b) {
    asm volatile(
        "mma.sync.aligned.m16n8k16.row.col.f32.bf16.bf16.f32 "
        "{%0,%1,%2,%3},{%4,%5,%6,%7},{%8,%9},{%0,%1,%2,%3};"
        : "+f"(c[0]), "+f"(c[1]), "+f"(c[2]), "+f"(c[3])
        : "r"(a[0]), "r"(a[1]), "r"(a[2]), "r"(a[3]), "r"(b[0]), "r"(b[1]));
}
__device__ __forceinline__ void bf16_split(float v, __nv_bfloat16& hi, __nv_bfloat16& lo) {
    hi = __float2bfloat16_rn(v);
    lo = __float2bfloat16_rn(v - __bfloat162float(hi));
}
__device__ __forceinline__ float sigmoidf1(float x) { return 1.f / (1.f + expf(-x)); }

// ================= templated bf16x3 TN GEMM =====================================
// C[m,n] = sum_k A[m,k]*B[n,k], A = Ah+Al, B = Bh+Bl (bf16 2-term splits).
// C += Al*Bh + Ah*Bl + Ah*Bh  (fp32 accumulate; per-acc order preserved)
// TBN: CTA tile N; WM: warps along M (8/WM along N); MI/NI: m16/n8 frags per warp.
#define BM 128
#define BK 32
#define ROWS 40                      // smem row stride in bf16 (32 + 8 pad)

template<int TBN, int WM, int MI, int NI>
__global__ void __launch_bounds__(256, 2)
mma_gemm_bf16x3(const __nv_bfloat16* __restrict__ Ahg, const __nv_bfloat16* __restrict__ Alg,
                const __nv_bfloat16* __restrict__ Bhg, const __nv_bfloat16* __restrict__ Blg,
                const float* __restrict__ bias, const float* __restrict__ mask,
                float* __restrict__ C, int M, int N, int KT, int KP, int relu)
{
    constexpr int ABUF = 2 * BM * ROWS;      // both stages of one A matrix
    constexpr int BBUF = 2 * TBN * ROWS;
    constexpr int A_CHUNKS = BM * 4;         // 16B chunks per A matrix per tile
    constexpr int B_CHUNKS = TBN * 4;
    constexpr int TOT_CHUNKS = 2 * A_CHUNKS + 2 * B_CHUNKS;

    extern __shared__ __nv_bfloat16 smem[];
    __nv_bfloat16* Ah = smem;
    __nv_bfloat16* Al = smem + ABUF;
    __nv_bfloat16* Bh = smem + 2 * ABUF;
    __nv_bfloat16* Bl = smem + 2 * ABUF + BBUF;

    const int tid  = threadIdx.x;
    const int wid  = tid >> 5;
    const int lane = tid & 31;
    const int warp_m = wid % WM;
    const int warp_n = wid / WM;
    const int m0 = blockIdx.y * BM;
    const int n0 = blockIdx.x * TBN;
    const int mat = lane >> 3;
    const int rw  = lane & 7;

    float acc[MI][NI][4];
    #pragma unroll
    for (int mi = 0; mi < MI; mi++)
        #pragma unroll
        for (int ni = 0; ni < NI; ni++)
            #pragma unroll
            for (int r = 0; r < 4; r++) acc[mi][ni][r] = 0.f;

    auto load_tile = [&](int kt, int s) {
        const int k0 = kt * BK;
        const int sba = s * BM * ROWS;
        const int sbb = s * TBN * ROWS;
        #pragma unroll
        for (int i = 0; i < TOT_CHUNKS / 256; i++) {
            int idx = tid + i * 256;
            if (idx < A_CHUNKS) {
                int row = idx >> 2, kc = (idx & 3) * 8;
                unsigned d = smem_u32(&Ah[sba + row * ROWS + kc]);
                int gm = m0 + row;
                if (gm < M) cp16(d, Ahg + (size_t)gm * KP + k0 + kc);
                else        sts_zero16(d);
            } else if (idx < 2 * A_CHUNKS) {
                int j = idx - A_CHUNKS;
                int row = j >> 2, kc = (j & 3) * 8;
                unsigned d = smem_u32(&Al[sba + row * ROWS + kc]);
                int gm = m0 + row;
                if (gm < M) cp16(d, Alg + (size_t)gm * KP + k0 + kc);
                else        sts_zero16(d);
            } else if (idx < 2 * A_CHUNKS + B_CHUNKS) {
                int j = idx - 2 * A_CHUNKS;
                int row = j >> 2, kc = (j & 3) * 8;
                unsigned d = smem_u32(&Bh[sbb + row * ROWS + kc]);
                int gn = n0 + row;
                if (gn < N) cp16(d, Bhg + (size_t)gn * KP + k0 + kc);
                else        sts_zero16(d);
            } else {
                int j = idx - 2 * A_CHUNKS - B_CHUNKS;
                int row = j >> 2, kc = (j & 3) * 8;
                unsigned d = smem_u32(&Bl[sbb + row * ROWS + kc]);
                int gn = n0 + row;
                if (gn < N) cp16(d, Blg + (size_t)gn * KP + k0 + kc);
                else        sts_zero16(d);
            }
        }
    };

    load_tile(0, 0);
    cp_commit();

    for (int kt = 0; kt < KT; kt++) {
        cp_wait0();
        __syncthreads();
        const int cur = kt & 1;
        if (kt + 1 < KT) load_tile(kt + 1, cur ^ 1);
        cp_commit();
        const int sba = cur * BM * ROWS;
        const int sbb = cur * TBN * ROWS;

        #pragma unroll
        for (int kk = 0; kk < BK; kk += 16) {
            unsigned ah[MI][4], al[MI][4];
            #pragma unroll
            for (int mi = 0; mi < MI; mi++) {
                int arow = warp_m * (MI * 16) + mi * 16 + ((mat & 1) << 3) + rw;
                int acol = kk + ((mat >> 1) << 3);
                unsigned ad = smem_u32(&Ah[sba + arow * ROWS + acol]);
                ldsm_x4(ah[mi][0], ah[mi][1], ah[mi][2], ah[mi][3], ad);
                unsigned ad2 = smem_u32(&Al[sba + arow * ROWS + acol]);
                ldsm_x4(al[mi][0], al[mi][1], al[mi][2], al[mi][3], ad2);
            }
            unsigned bh[NI][2], bl[NI][2];
            #pragma unroll
            for (int g2 = 0; g2 < NI / 2; g2++) {
                int brow = warp_n * (NI * 8) + g2 * 16 + ((mat >> 1) << 3) + rw;
                int bcol = kk + ((mat & 1) << 3);
                unsigned r0, r1, r2, r3;
                unsigned bd = smem_u32(&Bh[sbb + brow * ROWS + bcol]);
                ldsm_x4(r0, r1, r2, r3, bd);
                bh[g2*2  ][0] = r0; bh[g2*2  ][1] = r1;
                bh[g2*2+1][0] = r2; bh[g2*2+1][1] = r3;
                unsigned bd2 = smem_u32(&Bl[sbb + brow * ROWS + bcol]);
                ldsm_x4(r0, r1, r2, r3, bd2);
                bl[g2*2  ][0] = r0; bl[g2*2  ][1] = r1;
                bl[g2*2+1][0] = r2; bl[g2*2+1][1] = r3;
            }
            // 3 passes; per-accumulator order: lo*hi, hi*lo, hi*hi (round-12 proven)
            #pragma unroll
            for (int mi = 0; mi < MI; mi++)
                #pragma unroll
                for (int ni = 0; ni < NI; ni++)
                    mma_bf16(acc[mi][ni], al[mi], bh[ni]);
            #pragma unroll
            for (int mi = 0; mi < MI; mi++)
                #pragma unroll
                for (int ni = 0; ni < NI; ni++)
                    mma_bf16(acc[mi][ni], ah[mi], bl[ni]);
            #pragma unroll
            for (int mi = 0; mi < MI; mi++)
                #pragma unroll
                for (int ni = 0; ni < NI; ni++)
                    mma_bf16(acc[mi][ni], ah[mi], bh[ni]);
        }
        // no trailing barrier (round-10/11 controlled comparison: mild positive)
    }

    // epilogue (minimal round-9 form)
    const int g = lane >> 2, t = lane & 3;
    #pragma unroll
    for (int mi = 0; mi < MI; mi++) {
        #pragma unroll
        for (int ni = 0; ni < NI; ni++) {
            int cn = n0 + warp_n * (NI * 8) + ni * 8 + 2 * t;
            float b0 = 0.f, b1 = 0.f;
            if (bias) {
                if (cn     < N) b0 = bias[cn];
                if (cn + 1 < N) b1 = bias[cn + 1];
            }
            #pragma unroll
            for (int half = 0; half < 2; half++) {
                int rm = m0 + warp_m * (MI * 16) + mi * 16 + g + half * 8;
                if (rm >= M) continue;
                float v0 = acc[mi][ni][half * 2 + 0] + b0;
                float v1 = acc[mi][ni][half * 2 + 1] + b1;
                if (relu) { v0 = fmaxf(v0, 0.f); v1 = fmaxf(v1, 0.f); }
                if (mask) { float mk = mask[rm]; v0 *= mk; v1 *= mk; }
                if (cn + 1 < N) {
                    float2 v = {v0, v1};
                    *(float2*)(C + (size_t)rm * N + cn) = v;
                } else if (cn < N) {
                    C[(size_t)rm * N + cn] = v0;
                }
            }
        }
    }
}

// instances: TBN=128 (2 warps M x 4 warps N, 64x32 warp tile) for N=300
//            TBN=96  (4 warps M x 2 warps N, 32x48 warp tile) for N=900
#define SMEMB_128 ((2 * 2 * BM * ROWS + 2 * 2 * 128 * ROWS) * 2)   // 81920
#define SMEMB_96  ((2 * 2 * BM * ROWS + 2 * 2 * 96  * ROWS) * 2)   // 71680

// ================= split producers ==============================================
__global__ void split_bf16(const float* __restrict__ src,
                           __nv_bfloat16* __restrict__ hi,
                           __nv_bfloat16* __restrict__ lo,
                           int M, int K, int KP)
{
    int idx = blockIdx.x * blockDim.x + threadIdx.x;
    if (idx >= M * KP) return;
    int m = idx / KP;
    int k = idx - m * KP;
    float v = (k < K) ? src[(size_t)m * K + k] : 0.f;
    __nv_bfloat16 h, l;
    bf16_split(v, h, l);
    hi[idx] = h;
    lo[idx] = l;
}

#define W1_END (HID * KP_BOND)
#define W2_END (W1_END + 3 * HID * KP_HID)
#define W3_END (W2_END + 3 * HID * KP_HID)
#define W4_END (W3_END + HID * KP_CAT)
__global__ void split_weights_all(const float* __restrict__ W_i,
                                  const float* __restrict__ W_ih,
                                  const float* __restrict__ W_hh,
                                  const float* __restrict__ W_o,
                                  __nv_bfloat16* __restrict__ Wi_hi, __nv_bfloat16* __restrict__ Wi_lo,
                                  __nv_bfloat16* __restrict__ Wih_hi, __nv_bfloat16* __restrict__ Wih_lo,
                                  __nv_bfloat16* __restrict__ Whh_hi, __nv_bfloat16* __restrict__ Whh_lo,
                                  __nv_bfloat16* __restrict__ Wo_hi, __nv_bfloat16* __restrict__ Wo_lo)
{
    int idx = blockIdx.x * blockDim.x + threadIdx.x;
    if (idx >= W4_END) return;
    const float* src; __nv_bfloat16 *hi, *lo;
    int off, K, KP;
    if (idx < W1_END)      { src = W_i;  hi = Wi_hi;  lo = Wi_lo;  off = idx;          K = BOND_FDIM; KP = KP_BOND; }
    else if (idx < W2_END) { src = W_ih; hi = Wih_hi; lo = Wih_lo; off = idx - W1_END; K = HID;       KP = KP_HID; }
    else if (idx < W3_END) { src = W_hh; hi = Whh_hi; lo = Whh_lo; off = idx - W2_END; K = HID;       KP = KP_HID; }
    else                   { src = W_o;  hi = Wo_hi;  lo = Wo_lo;  off = idx - W3_END; K = CAT_DIM;   KP = KP_CAT; }
    int m = off / KP;
    int k = off - m * KP;
    float v = (k < K) ? src[(size_t)m * K + k] : 0.f;
    __nv_bfloat16 h, l;
    bf16_split(v, h, l);
    hi[off] = h;
    lo[off] = l;
}

__global__ void zero_pad_h(__nv_bfloat16* __restrict__ hi, __nv_bfloat16* __restrict__ lo)
{
    int idx = blockIdx.x * blockDim.x + threadIdx.x;
    const int PADW = KP_HID - HID;
    if (idx >= N_BONDS * PADW) return;
    int b = idx / PADW;
    int k = HID + (idx - b * PADW);
    hi[(size_t)b * KP_HID + k] = __float2bfloat16(0.f);
    lo[(size_t)b * KP_HID + k] = __float2bfloat16(0.f);
}

// ================= elementwise ==================================================
__global__ void gather_sum4(const float4* __restrict__ msg,
                            const int* __restrict__ a2b,
                            float4* __restrict__ amsg)
{
    int idx = blockIdx.x * blockDim.x + threadIdx.x;
    if (idx >= N_ATOMS * H4) return;
    int a = idx / H4;
    int j = idx - a * H4;
    const int* nb = a2b + (size_t)a * MAX_NB;
    float4 s = {0.f, 0.f, 0.f, 0.f};
    #pragma unroll
    for (int i = 0; i < MAX_NB; i++) {
        float4 v = msg[(size_t)nb[i] * H4 + j];
        s.x += v.x; s.y += v.y; s.z += v.z; s.w += v.w;
    }
    amsg[idx] = s;
}

__global__ void hpre4_split(const float4* __restrict__ amsg,
                            const float4* __restrict__ msg,
                            const int* __restrict__ b2a,
                            const int* __restrict__ b2revb,
                            __nv_bfloat162* __restrict__ h_hi,
                            __nv_bfloat162* __restrict__ h_lo)
{
    int idx = blockIdx.x * blockDim.x + threadIdx.x;
    if (idx >= N_BONDS * H4) return;
    int b = idx / H4;
    int j = idx - b * H4;
    float4 u = amsg[(size_t)b2a[b] * H4 + j];
    float4 v = msg[(size_t)b2revb[b] * H4 + j];
    float4 o = {u.x - v.x, u.y - v.y, u.z - v.z, u.w - v.w};
    __nv_bfloat16 hx, lx, hy, ly, hz, lz, hw, lw;
    bf16_split(o.x, hx, lx);
    bf16_split(o.y, hy, ly);
    bf16_split(o.z, hz, lz);
    bf16_split(o.w, hw, lw);
    size_t base = (size_t)b * (KP_HID / 2) + j * 2;
    h_hi[base]     = __nv_bfloat162(hx, hy);
    h_hi[base + 1] = __nv_bfloat162(hz, hw);
    h_lo[base]     = __nv_bfloat162(lx, ly);
    h_lo[base + 1] = __nv_bfloat162(lz, lw);
}

__global__ void gru4(const float4* __restrict__ gi,
                     const float4* __restrict__ gh,
                     const __nv_bfloat162* __restrict__ h_hi,
                     const __nv_bfloat162* __restrict__ h_lo,
                     float4* __restrict__ out)
{
    int idx = blockIdx.x * blockDim.x + threadIdx.x;
    if (idx >= N_BONDS * H4) return;
    int b = idx / H4;
    int j = idx - b * H4;
    if (b == 0) { out[idx] = make_float4(0.f, 0.f, 0.f, 0.f); return; }
    size_t gb = (size_t)b * H34;
    float4 ir = gi[gb + j], iz = gi[gb + H4 + j], in4 = gi[gb + 2 * H4 + j];
    float4 hr = gh[gb + j], hz = gh[gb + H4 + j], hn4 = gh[gb + 2 * H4 + j];
    size_t hb = (size_t)b * (KP_HID / 2) + j * 2;
    __nv_bfloat162 a0 = h_hi[hb], a1 = h_hi[hb + 1];
    __nv_bfloat162 c0 = h_lo[hb], c1 = h_lo[hb + 1];
    float4 hh;
    hh.x = __bfloat162float(a0.x) + __bfloat162float(c0.x);
    hh.y = __bfloat162float(a0.y) + __bfloat162float(c0.y);
    hh.z = __bfloat162float(a1.x) + __bfloat162float(c1.x);
    hh.w = __bfloat162float(a1.y) + __bfloat162float(c1.y);
    float4 o;
    {
        float r = sigmoidf1(ir.x + hr.x), z = sigmoidf1(iz.x + hz.x);
        float n = tanhf(in4.x + r * hn4.x);
        o.x = (1.f - z) * n + z * hh.x;
    }
    {
        float r = sigmoidf1(ir.y + hr.y), z = sigmoidf1(iz.y + hz.y);
        float n = tanhf(in4.y + r * hn4.y);
        o.y = (1.f - z) * n + z * hh.y;
    }
    {
        float r = sigmoidf1(ir.z + hr.z), z = sigmoidf1(iz.z + hz.z);
        float n = tanhf(in4.z + r * hn4.z);
        o.z = (1.f - z) * n + z * hh.z;
    }
    {
        float r = sigmoidf1(ir.w + hr.w), z = sigmoidf1(iz.w + hz.w);
        float n = tanhf(in4.w + r * hn4.w);
        o.w = (1.f - z) * n + z * hh.w;
    }
    out[idx] = o;
}

__global__ void concat_split(const float* __restrict__ f_atoms,
                             const float* __restrict__ amsg,
                             __nv_bfloat16* __restrict__ ain_hi,
                             __nv_bfloat16* __restrict__ ain_lo)
{
    int idx = blockIdx.x * blockDim.x + threadIdx.x;
    if (idx >= N_ATOMS * KP_CAT) return;
    int a = idx / KP_CAT;
    int k = idx - a * KP_CAT;
    float v = 0.f;
    if (k < ATOM_FDIM)      v = f_atoms[(size_t)a * ATOM_FDIM + k];
    else if (k < CAT_DIM)   v = amsg[(size_t)a * HID + (k - ATOM_FDIM)];
    __nv_bfloat16 h, l;
    bf16_split(v, h, l);
    ain_hi[idx] = h;
    ain_lo[idx] = l;
}

// ================= launch ========================================================
extern "C" void kernel_launch(void* const* d_in, const int* in_sizes, int n_in,
                              void* d_out, int out_size)
{
    const float* f_atoms = (const float*)d_in[0];
    const float* f_bonds = (const float*)d_in[1];
    const int*   a2b     = (const int*)  d_in[2];
    const int*   b2a     = (const int*)  d_in[3];
    const int*   b2revb  = (const int*)  d_in[4];
    const float* mask    = (const float*)d_in[8];
    const float* W_i     = (const float*)d_in[9];   // [300,147]
    const float* W_ih    = (const float*)d_in[10];  // [900,300]
    const float* W_hh    = (const float*)d_in[11];  // [900,300]
    const float* b_ih    = (const float*)d_in[12];
    const float* b_hh    = (const float*)d_in[13];
    const float* W_o_w   = (const float*)d_in[14];  // [300,433]
    const float* W_o_b   = (const float*)d_in[15];
    float* out = (float*)d_out;

    float *p_inp, *p_gi, *p_msg, *p_gh, *p_amsg;
    __nv_bfloat16 *p_fb_hi, *p_fb_lo, *p_inp_hi, *p_inp_lo, *p_h_hi, *p_h_lo;
    __nv_bfloat16 *p_ain_hi, *p_ain_lo;
    __nv_bfloat16 *p_Wi_hi, *p_Wi_lo, *p_Wih_hi, *p_Wih_lo, *p_Whh_hi, *p_Whh_lo;
    __nv_bfloat16 *p_Wo_hi, *p_Wo_lo;
    cudaGetSymbolAddress((void**)&p_inp,    g_inp);
    cudaGetSymbolAddress((void**)&p_gi,     g_gi);
    cudaGetSymbolAddress((void**)&p_msg,    g_msg);
    cudaGetSymbolAddress((void**)&p_gh,     g_gh);
    cudaGetSymbolAddress((void**)&p_amsg,   g_amsg);
    cudaGetSymbolAddress((void**)&p_fb_hi,  g_fb_hi);
    cudaGetSymbolAddress((void**)&p_fb_lo,  g_fb_lo);
    cudaGetSymbolAddress((void**)&p_inp_hi, g_inp_hi);
    cudaGetSymbolAddress((void**)&p_inp_lo, g_inp_lo);
    cudaGetSymbolAddress((void**)&p_h_hi,   g_h_hi);
    cudaGetSymbolAddress((void**)&p_h_lo,   g_h_lo);
    cudaGetSymbolAddress((void**)&p_ain_hi, g_ain_hi);
    cudaGetSymbolAddress((void**)&p_ain_lo, g_ain_lo);
    cudaGetSymbolAddress((void**)&p_Wi_hi,  g_Wi_hi);
    cudaGetSymbolAddress((void**)&p_Wi_lo,  g_Wi_lo);
    cudaGetSymbolAddress((void**)&p_Wih_hi, g_Wih_hi);
    cudaGetSymbolAddress((void**)&p_Wih_lo, g_Wih_lo);
    cudaGetSymbolAddress((void**)&p_Whh_hi, g_Whh_hi);
    cudaGetSymbolAddress((void**)&p_Whh_lo, g_Whh_lo);
    cudaGetSymbolAddress((void**)&p_Wo_hi,  g_Wo_hi);
    cudaGetSymbolAddress((void**)&p_Wo_lo,  g_Wo_lo);

    static bool attr_set = false;
    if (!attr_set) {
        cudaFuncSetAttribute(mma_gemm_bf16x3<128, 2, 4, 4>,
                             cudaFuncAttributeMaxDynamicSharedMemorySize, SMEMB_128);
        cudaFuncSetAttribute(mma_gemm_bf16x3<96, 4, 2, 6>,
                             cudaFuncAttributeMaxDynamicSharedMemorySize, SMEMB_96);
        attr_set = true;
    }

    const int EW = 256;
    int nb4_grid = (N_BONDS * H4 + EW - 1) / EW;
    int na4_grid = (N_ATOMS * H4 + EW - 1) / EW;
    auto sgrid = [](long n) { return (int)((n + 255) / 256); };

    const int MB_BONDS = (N_BONDS + BM - 1) / BM;   // 704
    const int MB_ATOMS = (N_ATOMS + BM - 1) / BM;   // 313
    dim3 grid_n300_b((300 + 127) / 128, MB_BONDS);  // 3 x 704
    dim3 grid_n900_b((900 + 95) / 96, MB_BONDS);    // 10 x 704
    dim3 grid_n300_a((300 + 127) / 128, MB_ATOMS);  // 3 x 313

    // 1. split f_bonds
    split_bf16<<<sgrid((long)N_BONDS * KP_BOND), 256>>>(f_bonds, p_fb_hi, p_fb_lo,
                                                        N_BONDS, BOND_FDIM, KP_BOND);
    // 2. split all weights
    split_weights_all<<<sgrid((long)W4_END), 256>>>(
        W_i, W_ih, W_hh, W_o_w,
        p_Wi_hi, p_Wi_lo, p_Wih_hi, p_Wih_lo,
        p_Whh_hi, p_Whh_lo, p_Wo_hi, p_Wo_lo);
    // 3. zero h pad columns
    zero_pad_h<<<sgrid((long)N_BONDS * (KP_HID - HID)), 256>>>(p_h_hi, p_h_lo);

    // 4. inp = f_bonds @ W_i^T         [90000,300] KP=160 (KT=5)
    mma_gemm_bf16x3<128, 2, 4, 4><<<grid_n300_b, 256, SMEMB_128>>>(
        p_fb_hi, p_fb_lo, p_Wi_hi, p_Wi_lo, nullptr, nullptr,
        p_inp, N_BONDS, HID, KP_BOND / BK, KP_BOND, 0);

    // 5. split inp
    split_bf16<<<sgrid((long)N_BONDS * KP_HID), 256>>>(p_inp, p_inp_hi, p_inp_lo,
                                                       N_BONDS, HID, KP_HID);

    // 6. gi = inp @ W_ih^T + b_ih      [90000,900] KP=320 (KT=10)  <- ncu target
    mma_gemm_bf16x3<96, 4, 2, 6><<<grid_n900_b, 256, SMEMB_96>>>(
        p_inp_hi, p_inp_lo, p_Wih_hi, p_Wih_lo, b_ih, nullptr,
        p_gi, N_BONDS, 3 * HID, KP_HID / BK, KP_HID, 0);

    const float* msg_src = p_inp;
    for (int it = 0; it < DEPTH - 1; it++) {
        gather_sum4<<<na4_grid, EW>>>((const float4*)msg_src, a2b, (float4*)p_amsg);
        hpre4_split<<<nb4_grid, EW>>>((const float4*)p_amsg, (const float4*)msg_src,
                                      b2a, b2revb,
                                      (__nv_bfloat162*)p_h_hi, (__nv_bfloat162*)p_h_lo);
        // gh = h @ W_hh^T + b_hh       [90000,900] K=300
        mma_gemm_bf16x3<96, 4, 2, 6><<<grid_n900_b, 256, SMEMB_96>>>(
            p_h_hi, p_h_lo, p_Whh_hi, p_Whh_lo, b_hh, nullptr,
            p_gh, N_BONDS, 3 * HID, KP_HID / BK, KP_HID, 0);
        gru4<<<nb4_grid, EW>>>((const float4*)p_gi, (const float4*)p_gh,
                               (const __nv_bfloat162*)p_h_hi,
                               (const __nv_bfloat162*)p_h_lo, (float4*)p_msg);
        msg_src = p_msg;
    }

    gather_sum4<<<na4_grid, EW>>>((const float4*)msg_src, a2b, (float4*)p_amsg);
    concat_split<<<sgrid((long)N_ATOMS * KP_CAT), 256>>>(f_atoms, p_amsg,
                                                         p_ain_hi, p_ain_lo);
    // out = relu(ain @ W_o_w^T + W_o_b) * mask   [40000,300] KP=448 (KT=14)
    mma_gemm_bf16x3<128, 2, 4, 4><<<grid_n300_a, 256, SMEMB_128>>>(
        p_ain_hi, p_ain_lo, p_Wo_hi, p_Wo_lo, W_o_b, mask,
        out, N_ATOMS, HID, KP_CAT / BK, KP_CAT, 1);
}

// round 14
// speedup vs baseline: 1.0799x; 1.0114x over previous
#include <cuda_runtime.h>
#include <cuda_bf16.h>
#include <math.h>
#include <stdint.h>

#define N_ATOMS 40000
#define N_BONDS 90000
#define MAX_NB 6
#define ATOM_FDIM 133
#define BOND_FDIM 147
#define HID 300
#define DEPTH 6
#define CAT_DIM (ATOM_FDIM + HID)   // 433

#define H4   (HID / 4)              // 75
#define H34  (3 * HID / 4)          // 225

// padded K strides (multiples of 32) for bf16 split operands
#define KP_BOND 160                 // 147 -> 160
#define KP_HID  320                 // 300 -> 320
#define KP_CAT  448                 // 433 -> 448

// ---------------- scratch (device globals; no cudaMalloc allowed) -------------
__device__ float g_inp [N_BONDS * HID];
__device__ float g_gi  [N_BONDS * 3 * HID];
__device__ float g_msg [N_BONDS * HID];
__device__ float g_gh  [N_BONDS * 3 * HID];
__device__ float g_amsg[N_ATOMS * HID];

__device__ __nv_bfloat16 g_fb_hi [N_BONDS * KP_BOND];
__device__ __nv_bfloat16 g_fb_lo [N_BONDS * KP_BOND];
__device__ __nv_bfloat16 g_inp_hi[N_BONDS * KP_HID];
__device__ __nv_bfloat16 g_inp_lo[N_BONDS * KP_HID];
__device__ __nv_bfloat16 g_h_hi  [N_BONDS * KP_HID];
__device__ __nv_bfloat16 g_h_lo  [N_BONDS * KP_HID];
__device__ __nv_bfloat16 g_ain_hi[N_ATOMS * KP_CAT];
__device__ __nv_bfloat16 g_ain_lo[N_ATOMS * KP_CAT];
__device__ __nv_bfloat16 g_Wi_hi [HID * KP_BOND];
__device__ __nv_bfloat16 g_Wi_lo [HID * KP_BOND];
__device__ __nv_bfloat16 g_Wih_hi[3 * HID * KP_HID];
__device__ __nv_bfloat16 g_Wih_lo[3 * HID * KP_HID];
__device__ __nv_bfloat16 g_Whh_hi[3 * HID * KP_HID];
__device__ __nv_bfloat16 g_Whh_lo[3 * HID * KP_HID];
__device__ __nv_bfloat16 g_Wo_hi [HID * KP_CAT];
__device__ __nv_bfloat16 g_Wo_lo [HID * KP_CAT];

// ================= helpers ======================================================
__device__ __forceinline__ unsigned smem_u32(const void* p) {
    return (unsigned)__cvta_generic_to_shared(p);
}
__device__ __forceinline__ void cp16(unsigned dst, const void* src) {
    asm volatile("cp.async.cg.shared.global [%0], [%1], 16;\n" :: "r"(dst), "l"(src));
}
__device__ __forceinline__ void cp_commit() { asm volatile("cp.async.commit_group;\n"); }
__device__ __forceinline__ void cp_wait0()  { asm volatile("cp.async.wait_group 0;\n"); }
__device__ __forceinline__ void sts_zero16(unsigned dst) {
    asm volatile("st.shared.v4.b32 [%0], {%1,%1,%1,%1};" :: "r"(dst), "r"(0));
}
__device__ __forceinline__ void ldsm_x4(unsigned& r0, unsigned& r1, unsigned& r2,
                                        unsigned& r3, unsigned addr) {
    asm volatile("ldmatrix.sync.aligned.m8n8.x4.shared.b16 {%0,%1,%2,%3}, [%4];"
                 : "=r"(r0), "=r"(r1), "=r"(r2), "=r"(r3) : "r"(addr));
}
__device__ __forceinline__ void mma_bf16(float* c, const unsigned* a, const unsigned* b) {
    asm volatile(
        "mma.sync.aligned.m16n8k16.row.col.f32.bf16.bf16.f32 "
        "{%0,%1,%2,%3},{%4,%5,%6,%7},{%8,%9},{%0,%1,%2,%3};"
        : "+f"(c[0]), "+f"(c[1]), "+f"(c[2]), "+f"(c[3])
        : "r"(a[0]), "r"(a[1]), "r"(a[2]), "r"(a[3]), "r"(b[0]), "r"(b[1]));
}
__device__ __forceinline__ void bf16_split(float v, __nv_bfloat16& hi, __nv_bfloat16& lo) {
    hi = __float2bfloat16_rn(v);
    lo = __float2bfloat16_rn(v - __bfloat162float(hi));
}
__device__ __forceinline__ float sigmoidf1(float x) { return 1.f / (1.f + expf(-x)); }

// ================= templated bf16x3 TN GEMM =====================================
// C[m,n] = sum_k A[m,k]*B[n,k], A = Ah+Al, B = Bh+Bl (bf16 2-term splits).
// C += Al*Bh + Ah*Bl + Ah*Bh  (fp32 accumulate; per-acc order preserved)
// SPLIT_OUT: also emit bf16 split of C into Chi/Clo at stride KPo (cold instances only)
#define BM 128
#define BK 32
#define ROWS 40                      // smem row stride in bf16 (32 + 8 pad)

template<int TBN, int WM, int MI, int NI, bool SPLIT_OUT>
__global__ void __launch_bounds__(256, 2)
mma_gemm_bf16x3(const __nv_bfloat16* __restrict__ Ahg, const __nv_bfloat16* __restrict__ Alg,
                const __nv_bfloat16* __restrict__ Bhg, const __nv_bfloat16* __restrict__ Blg,
                const float* __restrict__ bias, const float* __restrict__ mask,
                __nv_bfloat16* __restrict__ Chi, __nv_bfloat16* __restrict__ Clo, int KPo,
                float* __restrict__ C, int M, int N, int KT, int KP, int relu)
{
    constexpr int ABUF = 2 * BM * ROWS;
    constexpr int BBUF = 2 * TBN * ROWS;
    constexpr int A_CHUNKS = BM * 4;
    constexpr int B_CHUNKS = TBN * 4;
    constexpr int TOT_CHUNKS = 2 * A_CHUNKS + 2 * B_CHUNKS;

    extern __shared__ __nv_bfloat16 smem[];
    __nv_bfloat16* Ah = smem;
    __nv_bfloat16* Al = smem + ABUF;
    __nv_bfloat16* Bh = smem + 2 * ABUF;
    __nv_bfloat16* Bl = smem + 2 * ABUF + BBUF;

    const int tid  = threadIdx.x;
    const int wid  = tid >> 5;
    const int lane = tid & 31;
    const int warp_m = wid % WM;
    const int warp_n = wid / WM;
    const int m0 = blockIdx.y * BM;
    const int n0 = blockIdx.x * TBN;
    const int mat = lane >> 3;
    const int rw  = lane & 7;

    float acc[MI][NI][4];
    #pragma unroll
    for (int mi = 0; mi < MI; mi++)
        #pragma unroll
        for (int ni = 0; ni < NI; ni++)
            #pragma unroll
            for (int r = 0; r < 4; r++) acc[mi][ni][r] = 0.f;

    auto load_tile = [&](int kt, int s) {
        const int k0 = kt * BK;
        const int sba = s * BM * ROWS;
        const int sbb = s * TBN * ROWS;
        #pragma unroll
        for (int i = 0; i < TOT_CHUNKS / 256; i++) {
            int idx = tid + i * 256;
            if (idx < A_CHUNKS) {
                int row = idx >> 2, kc = (idx & 3) * 8;
                unsigned d = smem_u32(&Ah[sba + row * ROWS + kc]);
                int gm = m0 + row;
                if (gm < M) cp16(d, Ahg + (size_t)gm * KP + k0 + kc);
                else        sts_zero16(d);
            } else if (idx < 2 * A_CHUNKS) {
                int j = idx - A_CHUNKS;
                int row = j >> 2, kc = (j & 3) * 8;
                unsigned d = smem_u32(&Al[sba + row * ROWS + kc]);
                int gm = m0 + row;
                if (gm < M) cp16(d, Alg + (size_t)gm * KP + k0 + kc);
                else        sts_zero16(d);
            } else if (idx < 2 * A_CHUNKS + B_CHUNKS) {
                int j = idx - 2 * A_CHUNKS;
                int row = j >> 2, kc = (j & 3) * 8;
                unsigned d = smem_u32(&Bh[sbb + row * ROWS + kc]);
                int gn = n0 + row;
                if (gn < N) cp16(d, Bhg + (size_t)gn * KP + k0 + kc);
                else        sts_zero16(d);
            } else {
                int j = idx - 2 * A_CHUNKS - B_CHUNKS;
                int row = j >> 2, kc = (j & 3) * 8;
                unsigned d = smem_u32(&Bl[sbb + row * ROWS + kc]);
                int gn = n0 + row;
                if (gn < N) cp16(d, Blg + (size_t)gn * KP + k0 + kc);
                else        sts_zero16(d);
            }
        }
    };

    load_tile(0, 0);
    cp_commit();

    for (int kt = 0; kt < KT; kt++) {
        cp_wait0();
        __syncthreads();
        const int cur = kt & 1;
        if (kt + 1 < KT) load_tile(kt + 1, cur ^ 1);
        cp_commit();
        const int sba = cur * BM * ROWS;
        const int sbb = cur * TBN * ROWS;

        #pragma unroll
        for (int kk = 0; kk < BK; kk += 16) {
            unsigned ah[MI][4], al[MI][4];
            #pragma unroll
            for (int mi = 0; mi < MI; mi++) {
                int arow = warp_m * (MI * 16) + mi * 16 + ((mat & 1) << 3) + rw;
                int acol = kk + ((mat >> 1) << 3);
                unsigned ad = smem_u32(&Ah[sba + arow * ROWS + acol]);
                ldsm_x4(ah[mi][0], ah[mi][1], ah[mi][2], ah[mi][3], ad);
                unsigned ad2 = smem_u32(&Al[sba + arow * ROWS + acol]);
                ldsm_x4(al[mi][0], al[mi][1], al[mi][2], al[mi][3], ad2);
            }
            unsigned bh[NI][2], bl[NI][2];
            #pragma unroll
            for (int g2 = 0; g2 < NI / 2; g2++) {
                int brow = warp_n * (NI * 8) + g2 * 16 + ((mat >> 1) << 3) + rw;
                int bcol = kk + ((mat & 1) << 3);
                unsigned r0, r1, r2, r3;
                unsigned bd = smem_u32(&Bh[sbb + brow * ROWS + bcol]);
                ldsm_x4(r0, r1, r2, r3, bd);
                bh[g2*2  ][0] = r0; bh[g2*2  ][1] = r1;
                bh[g2*2+1][0] = r2; bh[g2*2+1][1] = r3;
                unsigned bd2 = smem_u32(&Bl[sbb + brow * ROWS + bcol]);
                ldsm_x4(r0, r1, r2, r3, bd2);
                bl[g2*2  ][0] = r0; bl[g2*2  ][1] = r1;
                bl[g2*2+1][0] = r2; bl[g2*2+1][1] = r3;
            }
            // 3 passes; per-accumulator order: lo*hi, hi*lo, hi*hi
            #pragma unroll
            for (int mi = 0; mi < MI; mi++)
                #pragma unroll
                for (int ni = 0; ni < NI; ni++)
                    mma_bf16(acc[mi][ni], al[mi], bh[ni]);
            #pragma unroll
            for (int mi = 0; mi < MI; mi++)
                #pragma unroll
                for (int ni = 0; ni < NI; ni++)
                    mma_bf16(acc[mi][ni], ah[mi], bl[ni]);
            #pragma unroll
            for (int mi = 0; mi < MI; mi++)
                #pragma unroll
                for (int ni = 0; ni < NI; ni++)
                    mma_bf16(acc[mi][ni], ah[mi], bh[ni]);
        }
        // no trailing barrier (rounds 10/11 controlled comparison)
    }

    // epilogue
    const int g = lane >> 2, t = lane & 3;
    #pragma unroll
    for (int mi = 0; mi < MI; mi++) {
        #pragma unroll
        for (int ni = 0; ni < NI; ni++) {
            int cn = n0 + warp_n * (NI * 8) + ni * 8 + 2 * t;
            float b0 = 0.f, b1 = 0.f;
            if (bias) {
                if (cn     < N) b0 = bias[cn];
                if (cn + 1 < N) b1 = bias[cn + 1];
            }
            #pragma unroll
            for (int half = 0; half < 2; half++) {
                int rm = m0 + warp_m * (MI * 16) + mi * 16 + g + half * 8;
                if (rm >= M) continue;
                float v0 = acc[mi][ni][half * 2 + 0] + b0;
                float v1 = acc[mi][ni][half * 2 + 1] + b1;
                if (relu) { v0 = fmaxf(v0, 0.f); v1 = fmaxf(v1, 0.f); }
                if (mask) { float mk = mask[rm]; v0 *= mk; v1 *= mk; }
                if (cn + 1 < N) {
                    float2 v = {v0, v1};
                    *(float2*)(C + (size_t)rm * N + cn) = v;
                    if (SPLIT_OUT) {
                        __nv_bfloat16 h0, l0, h1, l1;
                        bf16_split(v0, h0, l0);
                        bf16_split(v1, h1, l1);
                        *(__nv_bfloat162*)(Chi + (size_t)rm * KPo + cn) = __nv_bfloat162(h0, h1);
                        *(__nv_bfloat162*)(Clo + (size_t)rm * KPo + cn) = __nv_bfloat162(l0, l1);
                    }
                } else if (cn < N) {
                    C[(size_t)rm * N + cn] = v0;
                    if (SPLIT_OUT) {
                        __nv_bfloat16 h0, l0;
                        bf16_split(v0, h0, l0);
                        Chi[(size_t)rm * KPo + cn] = h0;
                        Clo[(size_t)rm * KPo + cn] = l0;
                    }
                }
            }
        }
    }
}

#define SMEMB_128 ((2 * 2 * BM * ROWS + 2 * 2 * 128 * ROWS) * 2)   // 81920
#define SMEMB_96  ((2 * 2 * BM * ROWS + 2 * 2 * 96  * ROWS) * 2)   // 71680

// ================= split producers ==============================================
__global__ void split_bf16(const float* __restrict__ src,
                           __nv_bfloat16* __restrict__ hi,
                           __nv_bfloat16* __restrict__ lo,
                           int M, int K, int KP)
{
    int idx = blockIdx.x * blockDim.x + threadIdx.x;
    if (idx >= M * KP) return;
    int m = idx / KP;
    int k = idx - m * KP;
    float v = (k < K) ? src[(size_t)m * K + k] : 0.f;
    __nv_bfloat16 h, l;
    bf16_split(v, h, l);
    hi[idx] = h;
    lo[idx] = l;
}

#define W1_END (HID * KP_BOND)
#define W2_END (W1_END + 3 * HID * KP_HID)
#define W3_END (W2_END + 3 * HID * KP_HID)
#define W4_END (W3_END + HID * KP_CAT)
__global__ void split_weights_all(const float* __restrict__ W_i,
                                  const float* __restrict__ W_ih,
                                  const float* __restrict__ W_hh,
                                  const float* __restrict__ W_o,
                                  __nv_bfloat16* __restrict__ Wi_hi, __nv_bfloat16* __restrict__ Wi_lo,
                                  __nv_bfloat16* __restrict__ Wih_hi, __nv_bfloat16* __restrict__ Wih_lo,
                                  __nv_bfloat16* __restrict__ Whh_hi, __nv_bfloat16* __restrict__ Whh_lo,
                                  __nv_bfloat16* __restrict__ Wo_hi, __nv_bfloat16* __restrict__ Wo_lo)
{
    int idx = blockIdx.x * blockDim.x + threadIdx.x;
    if (idx >= W4_END) return;
    const float* src; __nv_bfloat16 *hi, *lo;
    int off, K, KP;
    if (idx < W1_END)      { src = W_i;  hi = Wi_hi;  lo = Wi_lo;  off = idx;          K = BOND_FDIM; KP = KP_BOND; }
    else if (idx < W2_END) { src = W_ih; hi = Wih_hi; lo = Wih_lo; off = idx - W1_END; K = HID;       KP = KP_HID; }
    else if (idx < W3_END) { src = W_hh; hi = Whh_hi; lo = Whh_lo; off = idx - W2_END; K = HID;       KP = KP_HID; }
    else                   { src = W_o;  hi = Wo_hi;  lo = Wo_lo;  off = idx - W3_END; K = CAT_DIM;   KP = KP_CAT; }
    int m = off / KP;
    int k = off - m * KP;
    float v = (k < K) ? src[(size_t)m * K + k] : 0.f;
    __nv_bfloat16 h, l;
    bf16_split(v, h, l);
    hi[off] = h;
    lo[off] = l;
}

// zero the pad columns [HID, KP_HID) of BOTH h and inp split pairs (one shot)
__global__ void zero_pads(__nv_bfloat16* __restrict__ h_hi, __nv_bfloat16* __restrict__ h_lo,
                          __nv_bfloat16* __restrict__ i_hi, __nv_bfloat16* __restrict__ i_lo)
{
    int idx = blockIdx.x * blockDim.x + threadIdx.x;
    const int PADW = KP_HID - HID;   // 20
    if (idx >= N_BONDS * PADW) return;
    int b = idx / PADW;
    int k = HID + (idx - b * PADW);
    size_t off = (size_t)b * KP_HID + k;
    __nv_bfloat16 z = __float2bfloat16(0.f);
    h_hi[off] = z; h_lo[off] = z;
    i_hi[off] = z; i_lo[off] = z;
}

// ================= elementwise ==================================================
__global__ void gather_sum4(const float4* __restrict__ msg,
                            const int* __restrict__ a2b,
                            float4* __restrict__ amsg)
{
    int idx = blockIdx.x * blockDim.x + threadIdx.x;
    if (idx >= N_ATOMS * H4) return;
    int a = idx / H4;
    int j = idx - a * H4;
    const int* nb = a2b + (size_t)a * MAX_NB;
    float4 s = {0.f, 0.f, 0.f, 0.f};
    #pragma unroll
    for (int i = 0; i < MAX_NB; i++) {
        float4 v = msg[(size_t)nb[i] * H4 + j];
        s.x += v.x; s.y += v.y; s.z += v.z; s.w += v.w;
    }
    amsg[idx] = s;
}

__global__ void hpre4_split(const float4* __restrict__ amsg,
                            const float4* __restrict__ msg,
                            const int* __restrict__ b2a,
                            const int* __restrict__ b2revb,
                            __nv_bfloat162* __restrict__ h_hi,
                            __nv_bfloat162* __restrict__ h_lo)
{
    int idx = blockIdx.x * blockDim.x + threadIdx.x;
    if (idx >= N_BONDS * H4) return;
    int b = idx / H4;
    int j = idx - b * H4;
    float4 u = amsg[(size_t)b2a[b] * H4 + j];
    float4 v = msg[(size_t)b2revb[b] * H4 + j];
    float4 o = {u.x - v.x, u.y - v.y, u.z - v.z, u.w - v.w};
    __nv_bfloat16 hx, lx, hy, ly, hz, lz, hw, lw;
    bf16_split(o.x, hx, lx);
    bf16_split(o.y, hy, ly);
    bf16_split(o.z, hz, lz);
    bf16_split(o.w, hw, lw);
    size_t base = (size_t)b * (KP_HID / 2) + j * 2;
    h_hi[base]     = __nv_bfloat162(hx, hy);
    h_hi[base + 1] = __nv_bfloat162(hz, hw);
    h_lo[base]     = __nv_bfloat162(lx, ly);
    h_lo[base + 1] = __nv_bfloat162(lz, lw);
}

__global__ void gru4(const float4* __restrict__ gi,
                     const float4* __restrict__ gh,
                     const __nv_bfloat162* __restrict__ h_hi,
                     const __nv_bfloat162* __restrict__ h_lo,
                     float4* __restrict__ out)
{
    int idx = blockIdx.x * blockDim.x + threadIdx.x;
    if (idx >= N_BONDS * H4) return;
    int b = idx / H4;
    int j = idx - b * H4;
    if (b == 0) { out[idx] = make_float4(0.f, 0.f, 0.f, 0.f); return; }
    size_t gb = (size_t)b * H34;
    float4 ir = gi[gb + j], iz = gi[gb + H4 + j], in4 = gi[gb + 2 * H4 + j];
    float4 hr = gh[gb + j], hz = gh[gb + H4 + j], hn4 = gh[gb + 2 * H4 + j];
    size_t hb = (size_t)b * (KP_HID / 2) + j * 2;
    __nv_bfloat162 a0 = h_hi[hb], a1 = h_hi[hb + 1];
    __nv_bfloat162 c0 = h_lo[hb], c1 = h_lo[hb + 1];
    float4 hh;
    hh.x = __bfloat162float(a0.x) + __bfloat162float(c0.x);
    hh.y = __bfloat162float(a0.y) + __bfloat162float(c0.y);
    hh.z = __bfloat162float(a1.x) + __bfloat162float(c1.x);
    hh.w = __bfloat162float(a1.y) + __bfloat162float(c1.y);
    float4 o;
    {
        float r = sigmoidf1(ir.x + hr.x), z = sigmoidf1(iz.x + hz.x);
        float n = tanhf(in4.x + r * hn4.x);
        o.x = (1.f - z) * n + z * hh.x;
    }
    {
        float r = sigmoidf1(ir.y + hr.y), z = sigmoidf1(iz.y + hz.y);
        float n = tanhf(in4.y + r * hn4.y);
        o.y = (1.f - z) * n + z * hh.y;
    }
    {
        float r = sigmoidf1(ir.z + hr.z), z = sigmoidf1(iz.z + hz.z);
        float n = tanhf(in4.z + r * hn4.z);
        o.z = (1.f - z) * n + z * hh.z;
    }
    {
        float r = sigmoidf1(ir.w + hr.w), z = sigmoidf1(iz.w + hz.w);
        float n = tanhf(in4.w + r * hn4.w);
        o.w = (1.f - z) * n + z * hh.w;
    }
    out[idx] = o;
}

__global__ void concat_split(const float* __restrict__ f_atoms,
                             const float* __restrict__ amsg,
                             __nv_bfloat16* __restrict__ ain_hi,
                             __nv_bfloat16* __restrict__ ain_lo)
{
    int idx = blockIdx.x * blockDim.x + threadIdx.x;
    if (idx >= N_ATOMS * KP_CAT) return;
    int a = idx / KP_CAT;
    int k = idx - a * KP_CAT;
    float v = 0.f;
    if (k < ATOM_FDIM)      v = f_atoms[(size_t)a * ATOM_FDIM + k];
    else if (k < CAT_DIM)   v = amsg[(size_t)a * HID + (k - ATOM_FDIM)];
    __nv_bfloat16 h, l;
    bf16_split(v, h, l);
    ain_hi[idx] = h;
    ain_lo[idx] = l;
}

// ================= launch ========================================================
extern "C" void kernel_launch(void* const* d_in, const int* in_sizes, int n_in,
                              void* d_out, int out_size)
{
    const float* f_atoms = (const float*)d_in[0];
    const float* f_bonds = (const float*)d_in[1];
    const int*   a2b     = (const int*)  d_in[2];
    const int*   b2a     = (const int*)  d_in[3];
    const int*   b2revb  = (const int*)  d_in[4];
    const float* mask    = (const float*)d_in[8];
    const float* W_i     = (const float*)d_in[9];
    const float* W_ih    = (const float*)d_in[10];
    const float* W_hh    = (const float*)d_in[11];
    const float* b_ih    = (const float*)d_in[12];
    const float* b_hh    = (const float*)d_in[13];
    const float* W_o_w   = (const float*)d_in[14];
    const float* W_o_b   = (const float*)d_in[15];
    float* out = (float*)d_out;

    float *p_inp, *p_gi, *p_msg, *p_gh, *p_amsg;
    __nv_bfloat16 *p_fb_hi, *p_fb_lo, *p_inp_hi, *p_inp_lo, *p_h_hi, *p_h_lo;
    __nv_bfloat16 *p_ain_hi, *p_ain_lo;
    __nv_bfloat16 *p_Wi_hi, *p_Wi_lo, *p_Wih_hi, *p_Wih_lo, *p_Whh_hi, *p_Whh_lo;
    __nv_bfloat16 *p_Wo_hi, *p_Wo_lo;
    cudaGetSymbolAddress((void**)&p_inp,    g_inp);
    cudaGetSymbolAddress((void**)&p_gi,     g_gi);
    cudaGetSymbolAddress((void**)&p_msg,    g_msg);
    cudaGetSymbolAddress((void**)&p_gh,     g_gh);
    cudaGetSymbolAddress((void**)&p_amsg,   g_amsg);
    cudaGetSymbolAddress((void**)&p_fb_hi,  g_fb_hi);
    cudaGetSymbolAddress((void**)&p_fb_lo,  g_fb_lo);
    cudaGetSymbolAddress((void**)&p_inp_hi, g_inp_hi);
    cudaGetSymbolAddress((void**)&p_inp_lo, g_inp_lo);
    cudaGetSymbolAddress((void**)&p_h_hi,   g_h_hi);
    cudaGetSymbolAddress((void**)&p_h_lo,   g_h_lo);
    cudaGetSymbolAddress((void**)&p_ain_hi, g_ain_hi);
    cudaGetSymbolAddress((void**)&p_ain_lo, g_ain_lo);
    cudaGetSymbolAddress((void**)&p_Wi_hi,  g_Wi_hi);
    cudaGetSymbolAddress((void**)&p_Wi_lo,  g_Wi_lo);
    cudaGetSymbolAddress((void**)&p_Wih_hi, g_Wih_hi);
    cudaGetSymbolAddress((void**)&p_Wih_lo, g_Wih_lo);
    cudaGetSymbolAddress((void**)&p_Whh_hi, g_Whh_hi);
    cudaGetSymbolAddress((void**)&p_Whh_lo, g_Whh_lo);
    cudaGetSymbolAddress((void**)&p_Wo_hi,  g_Wo_hi);
    cudaGetSymbolAddress((void**)&p_Wo_lo,  g_Wo_lo);

    static bool attr_set = false;
    if (!attr_set) {
        cudaFuncSetAttribute(mma_gemm_bf16x3<128, 2, 4, 4, true>,
                             cudaFuncAttributeMaxDynamicSharedMemorySize, SMEMB_128);
        cudaFuncSetAttribute(mma_gemm_bf16x3<128, 2, 4, 4, false>,
                             cudaFuncAttributeMaxDynamicSharedMemorySize, SMEMB_128);
        cudaFuncSetAttribute(mma_gemm_bf16x3<96, 4, 2, 6, false>,
                             cudaFuncAttributeMaxDynamicSharedMemorySize, SMEMB_96);
        attr_set = true;
    }

    const int EW = 256;
    int nb4_grid = (N_BONDS * H4 + EW - 1) / EW;
    int na4_grid = (N_ATOMS * H4 + EW - 1) / EW;
    auto sgrid = [](long n) { return (int)((n + 255) / 256); };

    const int MB_BONDS = (N_BONDS + BM - 1) / BM;   // 704
    const int MB_ATOMS = (N_ATOMS + BM - 1) / BM;   // 313
    dim3 grid_n300_b((300 + 127) / 128, MB_BONDS);
    dim3 grid_n900_b((900 + 95) / 96, MB_BONDS);
    dim3 grid_n300_a((300 + 127) / 128, MB_ATOMS);

    // 1. split f_bonds
    split_bf16<<<sgrid((long)N_BONDS * KP_BOND), 256>>>(f_bonds, p_fb_hi, p_fb_lo,
                                                        N_BONDS, BOND_FDIM, KP_BOND);
    // 2. split all weights
    split_weights_all<<<sgrid((long)W4_END), 256>>>(
        W_i, W_ih, W_hh, W_o_w,
        p_Wi_hi, p_Wi_lo, p_Wih_hi, p_Wih_lo,
        p_Whh_hi, p_Whh_lo, p_Wo_hi, p_Wo_lo);
    // 3. zero pad columns of h AND inp split buffers
    zero_pads<<<sgrid((long)N_BONDS * (KP_HID - HID)), 256>>>(p_h_hi, p_h_lo,
                                                              p_inp_hi, p_inp_lo);

    // 4. inp = f_bonds @ W_i^T  [90000,300] (fused bf16 split -> inp_hi/inp_lo)
    mma_gemm_bf16x3<128, 2, 4, 4, true><<<grid_n300_b, 256, SMEMB_128>>>(
        p_fb_hi, p_fb_lo, p_Wi_hi, p_Wi_lo, nullptr, nullptr,
        p_inp_hi, p_inp_lo, KP_HID,
        p_inp, N_BONDS, HID, KP_BOND / BK, KP_BOND, 0);

    // 5. gi = inp @ W_ih^T + b_ih  [90000,900]
    mma_gemm_bf16x3<96, 4, 2, 6, false><<<grid_n900_b, 256, SMEMB_96>>>(
        p_inp_hi, p_inp_lo, p_Wih_hi, p_Wih_lo, b_ih, nullptr,
        nullptr, nullptr, 0,
        p_gi, N_BONDS, 3 * HID, KP_HID / BK, KP_HID, 0);

    const float* msg_src = p_inp;
    for (int it = 0; it < DEPTH - 1; it++) {
        gather_sum4<<<na4_grid, EW>>>((const float4*)msg_src, a2b, (float4*)p_amsg);
        hpre4_split<<<nb4_grid, EW>>>((const float4*)p_amsg, (const float4*)msg_src,
                                      b2a, b2revb,
                                      (__nv_bfloat162*)p_h_hi, (__nv_bfloat162*)p_h_lo);
        // gh = h @ W_hh^T + b_hh   [90000,900]
        mma_gemm_bf16x3<96, 4, 2, 6, false><<<grid_n900_b, 256, SMEMB_96>>>(
            p_h_hi, p_h_lo, p_Whh_hi, p_Whh_lo, b_hh, nullptr,
            nullptr, nullptr, 0,
            p_gh, N_BONDS, 3 * HID, KP_HID / BK, KP_HID, 0);
        gru4<<<nb4_grid, EW>>>((const float4*)p_gi, (const float4*)p_gh,
                               (const __nv_bfloat162*)p_h_hi,
                               (const __nv_bfloat162*)p_h_lo, (float4*)p_msg);
        msg_src = p_msg;
    }

    gather_sum4<<<na4_grid, EW>>>((const float4*)msg_src, a2b, (float4*)p_amsg);
    concat_split<<<sgrid((long)N_ATOMS * KP_CAT), 256>>>(f_atoms, p_amsg,
                                                         p_ain_hi, p_ain_lo);
    // out = relu(ain @ W_o_w^T + W_o_b) * mask   [40000,300]
    mma_gemm_bf16x3<128, 2, 4, 4, false><<<grid_n300_a, 256, SMEMB_128>>>(
        p_ain_hi, p_ain_lo, p_Wo_hi, p_Wo_lo, W_o_b, mask,
        nullptr, nullptr, 0,
        out, N_ATOMS, HID, KP_CAT / BK, KP_CAT, 1);
}